// round 7
// baseline (speedup 1.0000x reference)
#include <cuda_runtime.h>
#include <math.h>

// Problem constants
#define Bn   128
#define Dn   256
#define Sn   512
#define Kn   50
#define Hn   256
#define NC   2
#define THRES 0.3f
#define BS   (Bn*Sn)          // 65536

// Output layout (float32):
//  [0..255] pred | [256] 0 | [257] concept_sim | [258] concept_far
//  [259..+B*S*K) topic_prob_nn | [3277059] ae_loss
#define OUT_NN   259
#define OUT_AE   (259 + Bn*Sn*Kn)   // 3277059

// ---------------- device scratch ----------------
__device__ float g_tvnT[Kn*Dn];            // normalized topic vectors, [K][D]
__device__ float g_tpn[(size_t)Kn*BS];     // topic_prob_n, [K][B*S]  (13.1 MB)
__device__ float g_xn[(size_t)BS*Dn];      // x_n, [B*S][D]           (64 MB)
__device__ float g_acc1[Bn*Hn];            // sum over s of rec1
__device__ float g_cand[Kn*128];           // per-part top-32 candidates
__device__ float g_ae;

// ---------------- init ----------------
__global__ void k_init() {
    int i = blockIdx.x*blockDim.x + threadIdx.x;
    if (i < Bn*Hn) g_acc1[i] = 0.f;
    if (i == 0) g_ae = 0.f;
}

// ---------------- tv normalization ----------------
__global__ void k_prep(const float* __restrict__ tv) {
    __shared__ float sred[256];
    int k = blockIdx.x, d = threadIdx.x;
    float v = tv[d*Kn + k];
    sred[d] = v*v;
    __syncthreads();
    for (int off = 128; off > 0; off >>= 1) {
        if (d < off) sred[d] += sred[d+off];
        __syncthreads();
    }
    float nrm = sqrtf(sred[0]);
    g_tvnT[k*Dn + d] = v / fmaxf(nrm, 1e-12f);
}

// ---------------- concept_far = (||sum_k tvn_k||^2 - K) / K^2 ----------------
__global__ void k_far(float* __restrict__ out) {
    __shared__ float sred[256];
    int d = threadIdx.x;
    float u = 0.f;
    for (int k = 0; k < Kn; k++) u += g_tvnT[k*Dn + d];
    sred[d] = u*u;
    __syncthreads();
    for (int off = 128; off > 0; off >>= 1) {
        if (d < off) sred[d] += sred[d+off];
        __syncthreads();
    }
    if (d == 0) out[258] = (sred[0] - (float)Kn) / (float)(Kn*Kn);
}

// ================= Kernel 1: topic path =================
// grid (8, 128): 64 s per block, 512 threads.
// dyn smem floats: xs[64][260] | tp[64][51] | red[512] | rn[64] | inv[64]
#define T_XS   0
#define T_TP   16640
#define T_RED  19904
#define T_RN   20416
#define T_INV  20480
#define T_TOT  20544      // floats -> 82176 bytes
__global__ void __launch_bounds__(512, 2)
k_topic(const float* __restrict__ f, float* __restrict__ out)
{
    extern __shared__ float sm[];
    float* xs  = sm + T_XS;
    float* tp  = sm + T_TP;
    float* red = sm + T_RED;
    float* rn  = sm + T_RN;
    float* inv = sm + T_INV;

    const int tid = threadIdx.x;
    const int b = blockIdx.y;
    const int s0 = blockIdx.x * 64;
    const int bs0 = b*Sn + s0;

    // coalesced load: f is [B,D,S]
    const float* fb = f + (size_t)b*Dn*Sn + s0;
    for (int i = tid; i < 64*Dn; i += 512) {
        int d = i >> 6, sl = i & 63;
        xs[sl*260 + d] = fb[(size_t)d*Sn + sl];
    }
    __syncthreads();

    // per-s inverse norms (8 partials of 32 d each), vector LDS
    {
        int s = tid & 63, part = tid >> 6;
        float a = 0.f;
        int d0 = part*32;
        #pragma unroll
        for (int d = d0; d < d0+32; d += 4) {
            float4 v = *reinterpret_cast<const float4*>(&xs[s*260+d]);
            a += v.x*v.x + v.y*v.y + v.z*v.z + v.w*v.w;
        }
        red[part*64 + s] = a;
    }
    __syncthreads();
    if (tid < 64) {
        float nsq = 0.f;
        #pragma unroll
        for (int p = 0; p < 8; p++) nsq += red[p*64 + tid];
        rn[tid] = 1.0f / fmaxf(sqrtf(nsq), 1e-12f);
    }
    __syncthreads();

    // write x_n scratch, coalesced [bs][d]
    for (int i = tid; i < 64*Dn; i += 512) {
        int sl = i >> 8, d = i & 255;
        g_xn[(size_t)(bs0+sl)*Dn + d] = xs[sl*260+d] * rn[sl];
    }

    // topic_prob: thread (s = tid&63, kg = tid>>6) handles k = kg + 8j
    const int s = tid & 63, kg = tid >> 6;
    float acc[7];
    #pragma unroll
    for (int j = 0; j < 7; j++) acc[j] = 0.f;
    for (int d = 0; d < Dn; d += 4) {
        float4 x = *reinterpret_cast<const float4*>(&xs[s*260+d]);
        #pragma unroll
        for (int j = 0; j < 7; j++) {
            int k = kg + 8*j;
            int kc = (k < Kn) ? k : 0;
            const float4 w = *reinterpret_cast<const float4*>(&g_tvnT[kc*Dn + d]);
            acc[j] += x.x*w.x + x.y*w.y + x.z*w.z + x.w*w.w;
        }
    }

    // threshold mask + per-s sum
    float am[7];
    {
        float rns = rn[s];
        float psum = 0.f;
        #pragma unroll
        for (int j = 0; j < 7; j++) {
            int k = kg + 8*j;
            if (k < Kn) {
                float tn = acc[j] * rns;
                g_tpn[(size_t)k*BS + bs0 + s] = tn;
                am[j] = (tn > THRES) ? acc[j] : 0.f;
                psum += am[j];
            } else am[j] = 0.f;
        }
        red[kg*64 + s] = psum;
    }
    __syncthreads();
    if (tid < 64) {
        float t = 0.f;
        #pragma unroll
        for (int p = 0; p < 8; p++) t += red[p*64 + tid];
        inv[tid] = 1.0f / (t + 0.001f + 1e-8f);
    }
    __syncthreads();
    {
        float iv = inv[s];
        #pragma unroll
        for (int j = 0; j < 7; j++) {
            int k = kg + 8*j;
            if (k < Kn) tp[s*51 + k] = am[j] * iv;
        }
    }
    __syncthreads();

    // write topic_prob_nn to out, coalesced
    {
        float* onn = out + OUT_NN + (size_t)bs0 * Kn;
        for (int i = tid; i < 64*Kn; i += 512) {
            int ss = i / 50, k = i - ss*50;
            onn[i] = tp[ss*51 + k];
        }
    }
}

// ================= Kernel 2: fused rec1 + rec2 + ae =================
// grid 1024, 256 threads; block = 64 bs-rows. Weights streamed via LDG with
// one-step manual prefetch; single-k mainloop keeps regs < 128 (no spills).
// dyn smem floats: nn_t[64][52] | r1[64][260]
#define R_NN   0
#define R_R1   (64*52)
#define R_TOT  (64*52 + 64*260)   // 19968 floats -> 79872 bytes
__global__ void __launch_bounds__(256, 2)
k_rec(const float* __restrict__ rv1, const float* __restrict__ rv2,
      const float* __restrict__ out)
{
    extern __shared__ float smr[];
    float* nn_t = smr + R_NN;     // [64][52]
    float* r1   = smr + R_R1;     // [64][260]

    const int tid = threadIdx.x;
    const int bs0 = blockIdx.x * 64;
    const int wid = tid >> 5, lane = tid & 31;
    const int d0 = lane * 8;
    const int row0 = 8*wid;

    // stage nn tile
    {
        const float* nnsrc = out + OUT_NN + (size_t)bs0 * Kn;
        for (int i = tid; i < 64*Kn; i += 256) {
            int ss = i / 50, k = i - ss*50;
            nn_t[ss*52 + k] = nnsrc[i];
        }
    }
    __syncthreads();

    unsigned long long acc[8][4];

    // ---- rec1: [64,50] x [50,256] ----
    {
        #pragma unroll
        for (int j = 0; j < 8; j++)
            #pragma unroll
            for (int q = 0; q < 4; q++) acc[j][q] = 0ull;

        ulonglong2 wa = *reinterpret_cast<const ulonglong2*>(&rv1[d0]);
        ulonglong2 wb = *reinterpret_cast<const ulonglong2*>(&rv1[d0 + 4]);
        #pragma unroll 1
        for (int k = 0; k < Kn; k++) {
            int kn = (k+1 < Kn) ? k+1 : k;
            ulonglong2 wan = *reinterpret_cast<const ulonglong2*>(&rv1[kn*Hn + d0]);
            ulonglong2 wbn = *reinterpret_cast<const ulonglong2*>(&rv1[kn*Hn + d0 + 4]);
            float av[8];
            #pragma unroll
            for (int j = 0; j < 8; j++) av[j] = nn_t[(row0+j)*52 + k];
            #pragma unroll
            for (int j = 0; j < 8; j++) {
                unsigned long long ap;
                asm("mov.b64 %0, {%1, %1};" : "=l"(ap) : "f"(av[j]));
                asm("fma.rn.f32x2 %0, %1, %2, %0;" : "+l"(acc[j][0]) : "l"(ap), "l"(wa.x));
                asm("fma.rn.f32x2 %0, %1, %2, %0;" : "+l"(acc[j][1]) : "l"(ap), "l"(wa.y));
                asm("fma.rn.f32x2 %0, %1, %2, %0;" : "+l"(acc[j][2]) : "l"(ap), "l"(wb.x));
                asm("fma.rn.f32x2 %0, %1, %2, %0;" : "+l"(acc[j][3]) : "l"(ap), "l"(wb.y));
            }
            wa = wan; wb = wbn;
        }

        // relu -> r1 smem; per-h column sums -> g_acc1
        float hs[8];
        #pragma unroll
        for (int i = 0; i < 8; i++) hs[i] = 0.f;
        #pragma unroll
        for (int j = 0; j < 8; j++) {
            float v[8];
            #pragma unroll
            for (int q = 0; q < 4; q++) {
                float lo, hi;
                asm("mov.b64 {%0, %1}, %2;" : "=f"(lo), "=f"(hi) : "l"(acc[j][q]));
                v[2*q]   = fmaxf(lo, 0.f);
                v[2*q+1] = fmaxf(hi, 0.f);
            }
            #pragma unroll
            for (int i = 0; i < 8; i++) hs[i] += v[i];
            float* dst = &r1[(row0+j)*260 + d0];
            *reinterpret_cast<float4*>(dst)     = make_float4(v[0],v[1],v[2],v[3]);
            *reinterpret_cast<float4*>(dst + 4) = make_float4(v[4],v[5],v[6],v[7]);
        }
        int b = bs0 >> 9;
        #pragma unroll
        for (int i = 0; i < 8; i++)
            atomicAdd(&g_acc1[b*Hn + d0 + i], hs[i]);
    }
    __syncthreads();

    // ---- rec2: [64,256] x [256,256], ae fused ----
    {
        #pragma unroll
        for (int j = 0; j < 8; j++)
            #pragma unroll
            for (int q = 0; q < 4; q++) acc[j][q] = 0ull;

        ulonglong2 wa = *reinterpret_cast<const ulonglong2*>(&rv2[d0]);
        ulonglong2 wb = *reinterpret_cast<const ulonglong2*>(&rv2[d0 + 4]);
        #pragma unroll 1
        for (int k = 0; k < Hn; k++) {
            int kn = (k+1 < Hn) ? k+1 : k;
            ulonglong2 wan = *reinterpret_cast<const ulonglong2*>(&rv2[kn*Dn + d0]);
            ulonglong2 wbn = *reinterpret_cast<const ulonglong2*>(&rv2[kn*Dn + d0 + 4]);
            float av[8];
            #pragma unroll
            for (int j = 0; j < 8; j++) av[j] = r1[(row0+j)*260 + k];
            #pragma unroll
            for (int j = 0; j < 8; j++) {
                unsigned long long ap;
                asm("mov.b64 %0, {%1, %1};" : "=l"(ap) : "f"(av[j]));
                asm("fma.rn.f32x2 %0, %1, %2, %0;" : "+l"(acc[j][0]) : "l"(ap), "l"(wa.x));
                asm("fma.rn.f32x2 %0, %1, %2, %0;" : "+l"(acc[j][1]) : "l"(ap), "l"(wa.y));
                asm("fma.rn.f32x2 %0, %1, %2, %0;" : "+l"(acc[j][2]) : "l"(ap), "l"(wb.x));
                asm("fma.rn.f32x2 %0, %1, %2, %0;" : "+l"(acc[j][3]) : "l"(ap), "l"(wb.y));
            }
            wa = wan; wb = wbn;
        }
    }

    // ae epilogue (rec2 never materialized)
    float aeacc = 0.f;
    #pragma unroll
    for (int j = 0; j < 8; j++) {
        size_t base = (size_t)(bs0 + row0 + j)*Dn + d0;
        float4 xa = *reinterpret_cast<const float4*>(&g_xn[base]);
        float4 xb = *reinterpret_cast<const float4*>(&g_xn[base+4]);
        float lo, hi, e;
        asm("mov.b64 {%0, %1}, %2;" : "=f"(lo), "=f"(hi) : "l"(acc[j][0]));
        e = xa.x - lo; aeacc += e*e;  e = xa.y - hi; aeacc += e*e;
        asm("mov.b64 {%0, %1}, %2;" : "=f"(lo), "=f"(hi) : "l"(acc[j][1]));
        e = xa.z - lo; aeacc += e*e;  e = xa.w - hi; aeacc += e*e;
        asm("mov.b64 {%0, %1}, %2;" : "=f"(lo), "=f"(hi) : "l"(acc[j][2]));
        e = xb.x - lo; aeacc += e*e;  e = xb.y - hi; aeacc += e*e;
        asm("mov.b64 {%0, %1}, %2;" : "=f"(lo), "=f"(hi) : "l"(acc[j][3]));
        e = xb.z - lo; aeacc += e*e;  e = xb.w - hi; aeacc += e*e;
    }
    #pragma unroll
    for (int off = 16; off > 0; off >>= 1)
        aeacc += __shfl_xor_sync(0xffffffffu, aeacc, off);
    if (lane == 0) atomicAdd(&g_ae, aeacc);
}

// ---------------- topk part: top-32 of 16384 per (concept, quarter) ----------------
__global__ void k_topk_part() {
    __shared__ float cand[32*256];
    __shared__ float rv[256];
    __shared__ int   ri[256];
    int t = threadIdx.x, k = blockIdx.x, part = blockIdx.y;
    const float* src = g_tpn + (size_t)k*BS + part*16384;

    float lv[32];
    #pragma unroll
    for (int i = 0; i < 32; i++) lv[i] = -3.4e38f;
    for (int i = 0; i < 64; i++) {
        float v = src[(i<<8) + t];
        if (v > lv[0]) {
            int p = 0;
            while (p < 31 && lv[p+1] < v) { lv[p] = lv[p+1]; p++; }
            lv[p] = v;
        }
    }
    #pragma unroll
    for (int i = 0; i < 32; i++) cand[i*256 + t] = lv[i];
    __syncthreads();

    int ptr = 31;
    for (int r = 0; r < 32; r++) {
        rv[t] = (ptr >= 0) ? cand[ptr*256 + t] : -3.4e38f;
        ri[t] = t;
        __syncthreads();
        for (int off = 128; off > 0; off >>= 1) {
            if (t < off && rv[t+off] > rv[t]) { rv[t] = rv[t+off]; ri[t] = ri[t+off]; }
            __syncthreads();
        }
        if (t == 0) g_cand[k*128 + part*32 + r] = rv[0];   // descending
        int win = ri[0];
        __syncthreads();
        if (t == win) ptr--;
    }
}

// ---------------- topk merge: 4-way merge of sorted 32-lists ----------------
__global__ void k_topk_merge(float* __restrict__ out) {
    __shared__ float vals[Kn*130];
    __shared__ float sred[64];
    int t = threadIdx.x;  // 64 threads
    for (int i = t; i < Kn*128; i += 64) {
        int k = i >> 7, r = i & 127;
        vals[k*130 + r] = g_cand[i];
    }
    __syncthreads();
    float lsum = 0.f;
    if (t < Kn) {
        const float* row = &vals[t*130];
        int p0 = 0, p1 = 0, p2 = 0, p3 = 0;
        for (int r = 0; r < 32; r++) {
            float v0 = (p0 < 32) ? row[p0]      : -3.4e38f;
            float v1 = (p1 < 32) ? row[32+p1]   : -3.4e38f;
            float v2 = (p2 < 32) ? row[64+p2]   : -3.4e38f;
            float v3 = (p3 < 32) ? row[96+p3]   : -3.4e38f;
            float m = fmaxf(fmaxf(v0, v1), fmaxf(v2, v3));
            lsum += m;
            if (m == v0)      p0++;
            else if (m == v1) p1++;
            else if (m == v2) p2++;
            else              p3++;
        }
    }
    sred[t] = lsum;
    __syncthreads();
    for (int off = 32; off > 0; off >>= 1) {
        if (t < off) sred[t] += sred[t+off];
        __syncthreads();
    }
    if (t == 0) out[257] = -sred[0] * (1.0f/(float)(Kn * (Bn/4)));
}

// ---------------- finalization ----------------
__global__ void k_final(const float* __restrict__ rv2, const float* __restrict__ Wc,
                        const float* __restrict__ bc, float* __restrict__ out) {
    __shared__ float w2c[Hn*NC];
    int t = threadIdx.x;   // 512 threads
    {
        int h = t >> 1, c = t & 1;
        float a = 0.f;
        for (int d = 0; d < Dn; d++) a += rv2[h*Dn + d] * Wc[d*NC + c];
        w2c[t] = a;
    }
    __syncthreads();
    if (t < Bn*NC) {
        int b = t >> 1, c = t & 1;
        float p = 0.f;
        for (int h = 0; h < Hn; h++) p += g_acc1[b*Hn + h] * w2c[h*NC + c];
        out[t] = p * (1.0f/(float)Sn) + bc[c];
    }
    if (t == 256) out[256] = 0.f;
    if (t == 257) out[OUT_AE] = g_ae * (1.0f/(float)(Bn*Sn*Dn));
}

// ---------------- launch ----------------
extern "C" void kernel_launch(void* const* d_in, const int* in_sizes, int n_in,
                              void* d_out, int out_size) {
    const float* f   = (const float*)d_in[0];
    const float* tv  = (const float*)d_in[2];
    const float* rv1 = (const float*)d_in[3];
    const float* rv2 = (const float*)d_in[4];
    const float* Wc  = (const float*)d_in[5];
    const float* bc  = (const float*)d_in[6];
    float* out = (float*)d_out;

    static int attr_set = 0;
    if (!attr_set) {
        cudaFuncSetAttribute(k_topic, cudaFuncAttributeMaxDynamicSharedMemorySize,
                             T_TOT * (int)sizeof(float));
        cudaFuncSetAttribute(k_rec, cudaFuncAttributeMaxDynamicSharedMemorySize,
                             R_TOT * (int)sizeof(float));
        attr_set = 1;
    }

    k_init<<<128, 256>>>();
    k_prep<<<50, 256>>>(tv);
    k_far<<<1, 256>>>(out);

    k_topic<<<dim3(8, 128), 512, T_TOT * sizeof(float)>>>(f, out);

    k_topk_part<<<dim3(50, 4), 256>>>();
    k_topk_merge<<<1, 64>>>(out);

    k_rec<<<1024, 256, R_TOT * sizeof(float)>>>(rv1, rv2, out);

    k_final<<<1, 512>>>(rv2, Wc, bc, out);
}

// round 9
// speedup vs baseline: 1.2316x; 1.2316x over previous
#include <cuda_runtime.h>
#include <math.h>

// Problem constants
#define Bn   128
#define Dn   256
#define Sn   512
#define Kn   50
#define Hn   256
#define NC   2
#define THRES 0.3f
#define BS   (Bn*Sn)          // 65536

// Output layout (float32):
//  [0..255] pred | [256] 0 | [257] concept_sim | [258] concept_far
//  [259..+B*S*K) topic_prob_nn | [3277059] ae_loss
#define OUT_NN   259
#define OUT_AE   (259 + Bn*Sn*Kn)   // 3277059

// ---------------- device scratch ----------------
__device__ float g_tvnT[Kn*Dn];            // normalized topic vectors, [K][D]
__device__ float g_tpn[(size_t)Kn*BS];     // topic_prob_n, [K][B*S]  (13.1 MB)
__device__ float g_xn[(size_t)BS*Dn];      // x_n, [B*S][D]           (64 MB)
__device__ float g_r1[(size_t)BS*Hn];      // relu(rec1), [B*S][H]    (64 MB)
__device__ float g_acc1[Bn*Hn];            // sum over s of rec1
__device__ float g_cand[Kn*128];           // per-part top-32 candidates
__device__ float g_ae;

// ---------------- init ----------------
__global__ void k_init() {
    int i = blockIdx.x*blockDim.x + threadIdx.x;
    if (i < Bn*Hn) g_acc1[i] = 0.f;
    if (i == 0) g_ae = 0.f;
}

// ---------------- tv normalization ----------------
__global__ void k_prep(const float* __restrict__ tv) {
    __shared__ float sred[256];
    int k = blockIdx.x, d = threadIdx.x;
    float v = tv[d*Kn + k];
    sred[d] = v*v;
    __syncthreads();
    for (int off = 128; off > 0; off >>= 1) {
        if (d < off) sred[d] += sred[d+off];
        __syncthreads();
    }
    float nrm = sqrtf(sred[0]);
    g_tvnT[k*Dn + d] = v / fmaxf(nrm, 1e-12f);
}

// ---------------- concept_far = (||sum_k tvn_k||^2 - K) / K^2 ----------------
__global__ void k_far(float* __restrict__ out) {
    __shared__ float sred[256];
    int d = threadIdx.x;
    float u = 0.f;
    for (int k = 0; k < Kn; k++) u += g_tvnT[k*Dn + d];
    sred[d] = u*u;
    __syncthreads();
    for (int off = 128; off > 0; off >>= 1) {
        if (d < off) sred[d] += sred[d+off];
        __syncthreads();
    }
    if (d == 0) out[258] = (sred[0] - (float)Kn) / (float)(Kn*Kn);
}

// ================= Kernel 1: topic path =================
// grid (8, 128): 64 s per block, 512 threads.
#define T_XS   0
#define T_TP   16640
#define T_RED  19904
#define T_RN   20416
#define T_INV  20480
#define T_TOT  20544      // floats -> 82176 bytes
__global__ void __launch_bounds__(512, 2)
k_topic(const float* __restrict__ f, float* __restrict__ out)
{
    extern __shared__ float sm[];
    float* xs  = sm + T_XS;
    float* tp  = sm + T_TP;
    float* red = sm + T_RED;
    float* rn  = sm + T_RN;
    float* inv = sm + T_INV;

    const int tid = threadIdx.x;
    const int b = blockIdx.y;
    const int s0 = blockIdx.x * 64;
    const int bs0 = b*Sn + s0;

    const float* fb = f + (size_t)b*Dn*Sn + s0;
    for (int i = tid; i < 64*Dn; i += 512) {
        int d = i >> 6, sl = i & 63;
        xs[sl*260 + d] = fb[(size_t)d*Sn + sl];
    }
    __syncthreads();

    {
        int s = tid & 63, part = tid >> 6;
        float a = 0.f;
        int d0 = part*32;
        #pragma unroll
        for (int d = d0; d < d0+32; d += 4) {
            float4 v = *reinterpret_cast<const float4*>(&xs[s*260+d]);
            a += v.x*v.x + v.y*v.y + v.z*v.z + v.w*v.w;
        }
        red[part*64 + s] = a;
    }
    __syncthreads();
    if (tid < 64) {
        float nsq = 0.f;
        #pragma unroll
        for (int p = 0; p < 8; p++) nsq += red[p*64 + tid];
        rn[tid] = 1.0f / fmaxf(sqrtf(nsq), 1e-12f);
    }
    __syncthreads();

    for (int i = tid; i < 64*Dn; i += 512) {
        int sl = i >> 8, d = i & 255;
        g_xn[(size_t)(bs0+sl)*Dn + d] = xs[sl*260+d] * rn[sl];
    }

    const int s = tid & 63, kg = tid >> 6;
    float acc[7];
    #pragma unroll
    for (int j = 0; j < 7; j++) acc[j] = 0.f;
    for (int d = 0; d < Dn; d += 4) {
        float4 x = *reinterpret_cast<const float4*>(&xs[s*260+d]);
        #pragma unroll
        for (int j = 0; j < 7; j++) {
            int k = kg + 8*j;
            int kc = (k < Kn) ? k : 0;
            const float4 w = *reinterpret_cast<const float4*>(&g_tvnT[kc*Dn + d]);
            acc[j] += x.x*w.x + x.y*w.y + x.z*w.z + x.w*w.w;
        }
    }

    float am[7];
    {
        float rns = rn[s];
        float psum = 0.f;
        #pragma unroll
        for (int j = 0; j < 7; j++) {
            int k = kg + 8*j;
            if (k < Kn) {
                float tn = acc[j] * rns;
                g_tpn[(size_t)k*BS + bs0 + s] = tn;
                am[j] = (tn > THRES) ? acc[j] : 0.f;
                psum += am[j];
            } else am[j] = 0.f;
        }
        red[kg*64 + s] = psum;
    }
    __syncthreads();
    if (tid < 64) {
        float t = 0.f;
        #pragma unroll
        for (int p = 0; p < 8; p++) t += red[p*64 + tid];
        inv[tid] = 1.0f / (t + 0.001f + 1e-8f);
    }
    __syncthreads();
    {
        float iv = inv[s];
        #pragma unroll
        for (int j = 0; j < 7; j++) {
            int k = kg + 8*j;
            if (k < Kn) tp[s*51 + k] = am[j] * iv;
        }
    }
    __syncthreads();

    {
        float* onn = out + OUT_NN + (size_t)bs0 * Kn;
        for (int i = tid; i < 64*Kn; i += 512) {
            int ss = i / 50, k = i - ss*50;
            onn[i] = tp[ss*51 + k];
        }
    }
}

// ================= Kernel 2: rec1 GEMM [65536,50]x[50,256]  (R5 version) =================
#define RS1_FLOATS (Kn*Hn + 64*52)
__global__ void __launch_bounds__(256, 2)
k_rec1(const float* __restrict__ rv1, const float* __restrict__ out)
{
    extern __shared__ float sm1[];
    float* w1  = sm1;                 // [50][256]
    float* a_t = sm1 + Kn*Hn;         // [64][52]

    const int tid = threadIdx.x;
    const int bs0 = blockIdx.x * 64;
    const int wid = tid >> 5, lane = tid & 31;
    const int d0 = lane * 8;

    for (int i = tid; i < Kn*Hn; i += 256) w1[i] = rv1[i];
    {
        const float* nnsrc = out + OUT_NN + (size_t)bs0 * Kn;
        for (int i = tid; i < 64*Kn; i += 256) {
            int ss = i / 50, k = i - ss*50;
            a_t[ss*52 + k] = nnsrc[i];
        }
    }
    __syncthreads();

    unsigned long long acc[8][4];
    #pragma unroll
    for (int j = 0; j < 8; j++)
        #pragma unroll
        for (int q = 0; q < 4; q++) acc[j][q] = 0ull;

    #pragma unroll 5
    for (int k2 = 0; k2 < Kn; k2 += 2) {
        float2 av[8];
        #pragma unroll
        for (int j = 0; j < 8; j++)
            av[j] = *reinterpret_cast<const float2*>(&a_t[(8*wid+j)*52 + k2]);
        #pragma unroll
        for (int kk = 0; kk < 2; kk++) {
            const ulonglong2 wa = *reinterpret_cast<const ulonglong2*>(&w1[(k2+kk)*Hn + d0]);
            const ulonglong2 wb = *reinterpret_cast<const ulonglong2*>(&w1[(k2+kk)*Hn + d0 + 4]);
            #pragma unroll
            for (int j = 0; j < 8; j++) {
                float aj = kk ? av[j].y : av[j].x;
                unsigned long long ap;
                asm("mov.b64 %0, {%1, %1};" : "=l"(ap) : "f"(aj));
                asm("fma.rn.f32x2 %0, %1, %2, %0;" : "+l"(acc[j][0]) : "l"(ap), "l"(wa.x));
                asm("fma.rn.f32x2 %0, %1, %2, %0;" : "+l"(acc[j][1]) : "l"(ap), "l"(wa.y));
                asm("fma.rn.f32x2 %0, %1, %2, %0;" : "+l"(acc[j][2]) : "l"(ap), "l"(wb.x));
                asm("fma.rn.f32x2 %0, %1, %2, %0;" : "+l"(acc[j][3]) : "l"(ap), "l"(wb.y));
            }
        }
    }

    float hs[8];
    #pragma unroll
    for (int i = 0; i < 8; i++) hs[i] = 0.f;
    #pragma unroll
    for (int j = 0; j < 8; j++) {
        float v[8];
        #pragma unroll
        for (int q = 0; q < 4; q++) {
            float lo, hi;
            asm("mov.b64 {%0, %1}, %2;" : "=f"(lo), "=f"(hi) : "l"(acc[j][q]));
            v[2*q]   = fmaxf(lo, 0.f);
            v[2*q+1] = fmaxf(hi, 0.f);
        }
        #pragma unroll
        for (int i = 0; i < 8; i++) hs[i] += v[i];
        size_t base = (size_t)(bs0 + 8*wid + j)*Hn + d0;
        *reinterpret_cast<float4*>(&g_r1[base])   = make_float4(v[0],v[1],v[2],v[3]);
        *reinterpret_cast<float4*>(&g_r1[base+4]) = make_float4(v[4],v[5],v[6],v[7]);
    }
    int b = bs0 >> 9;
    #pragma unroll
    for (int i = 0; i < 8; i++)
        atomicAdd(&g_acc1[b*Hn + d0 + i], hs[i]);
}

// ================= Kernel 3: rec2 GEMM + ae, cp.async double-buffered =================
// grid 1024, 256 threads; block = 64 bs-rows x 256 d; h chunks of 16, 2 buffers.
// static smem: a2[2][64*20] | w2[2][16*256]   (43 KB)
#define CH 16
__global__ void __launch_bounds__(256, 2)
k_rec2ae(const float* __restrict__ rv2)
{
    __shared__ float a2[2][64*20];
    __shared__ float w2[2][CH*256];

    const int tid = threadIdx.x;
    const int bs0 = blockIdx.x * 64;
    const int wid = tid >> 5, lane = tid & 31;
    const int d0 = lane * 8;
    const int row0 = 8*wid;

    // cp.async staging of chunk c into buffer buf
    auto stage = [&](int c, int buf) {
        // a tile: 64 rows x 16 h = 4KB, one 16B copy per thread
        {
            int r = tid >> 2, g = tid & 3;
            const float* src = &g_r1[(size_t)(bs0 + r)*Hn + c*CH + g*4];
            unsigned sdst = (unsigned)__cvta_generic_to_shared(&a2[buf][r*20 + g*4]);
            asm volatile("cp.async.ca.shared.global [%0], [%1], 16;\n"
                         :: "r"(sdst), "l"(src));
        }
        // w tile: 16 rows x 256 d = 16KB, four 16B copies per thread
        #pragma unroll
        for (int q = 0; q < 4; q++) {
            int idx = tid + q*256;
            int r = idx >> 6, g = idx & 63;
            const float* src = &rv2[(c*CH + r)*Dn + g*4];
            unsigned sdst = (unsigned)__cvta_generic_to_shared(&w2[buf][r*256 + g*4]);
            asm volatile("cp.async.ca.shared.global [%0], [%1], 16;\n"
                         :: "r"(sdst), "l"(src));
        }
        asm volatile("cp.async.commit_group;\n");
    };

    unsigned long long acc[8][4];
    #pragma unroll
    for (int j = 0; j < 8; j++)
        #pragma unroll
        for (int q = 0; q < 4; q++) acc[j][q] = 0ull;

    stage(0, 0);

    const int NCHUNK = Hn / CH;   // 16
    for (int c = 0; c < NCHUNK; c++) {
        if (c + 1 < NCHUNK) {
            stage(c + 1, (c + 1) & 1);
            asm volatile("cp.async.wait_group 1;\n");
        } else {
            asm volatile("cp.async.wait_group 0;\n");
        }
        __syncthreads();

        const float* at = a2[c & 1];
        const float* wt = w2[c & 1];
        #pragma unroll 4
        for (int k2 = 0; k2 < CH; k2 += 2) {
            float2 av[8];
            #pragma unroll
            for (int j = 0; j < 8; j++)
                av[j] = *reinterpret_cast<const float2*>(&at[(row0+j)*20 + k2]);
            #pragma unroll
            for (int kk = 0; kk < 2; kk++) {
                const ulonglong2 wa = *reinterpret_cast<const ulonglong2*>(&wt[(k2+kk)*256 + d0]);
                const ulonglong2 wb = *reinterpret_cast<const ulonglong2*>(&wt[(k2+kk)*256 + d0 + 4]);
                #pragma unroll
                for (int j = 0; j < 8; j++) {
                    float aj = kk ? av[j].y : av[j].x;
                    unsigned long long ap;
                    asm("mov.b64 %0, {%1, %1};" : "=l"(ap) : "f"(aj));
                    asm("fma.rn.f32x2 %0, %1, %2, %0;" : "+l"(acc[j][0]) : "l"(ap), "l"(wa.x));
                    asm("fma.rn.f32x2 %0, %1, %2, %0;" : "+l"(acc[j][1]) : "l"(ap), "l"(wa.y));
                    asm("fma.rn.f32x2 %0, %1, %2, %0;" : "+l"(acc[j][2]) : "l"(ap), "l"(wb.x));
                    asm("fma.rn.f32x2 %0, %1, %2, %0;" : "+l"(acc[j][3]) : "l"(ap), "l"(wb.y));
                }
            }
        }
        __syncthreads();
    }

    // ae epilogue (rec2 never materialized)
    float aeacc = 0.f;
    #pragma unroll
    for (int j = 0; j < 8; j++) {
        size_t base = (size_t)(bs0 + row0 + j)*Dn + d0;
        float4 xa = *reinterpret_cast<const float4*>(&g_xn[base]);
        float4 xb = *reinterpret_cast<const float4*>(&g_xn[base+4]);
        float lo, hi, e;
        asm("mov.b64 {%0, %1}, %2;" : "=f"(lo), "=f"(hi) : "l"(acc[j][0]));
        e = xa.x - lo; aeacc += e*e;  e = xa.y - hi; aeacc += e*e;
        asm("mov.b64 {%0, %1}, %2;" : "=f"(lo), "=f"(hi) : "l"(acc[j][1]));
        e = xa.z - lo; aeacc += e*e;  e = xa.w - hi; aeacc += e*e;
        asm("mov.b64 {%0, %1}, %2;" : "=f"(lo), "=f"(hi) : "l"(acc[j][2]));
        e = xb.x - lo; aeacc += e*e;  e = xb.y - hi; aeacc += e*e;
        asm("mov.b64 {%0, %1}, %2;" : "=f"(lo), "=f"(hi) : "l"(acc[j][3]));
        e = xb.z - lo; aeacc += e*e;  e = xb.w - hi; aeacc += e*e;
    }
    #pragma unroll
    for (int off = 16; off > 0; off >>= 1)
        aeacc += __shfl_xor_sync(0xffffffffu, aeacc, off);
    if (lane == 0) atomicAdd(&g_ae, aeacc);
}

// ---------------- topk part: top-32 of 16384 per (concept, quarter) ----------------
__global__ void k_topk_part() {
    __shared__ float cand[32*256];
    __shared__ float rv[256];
    __shared__ int   ri[256];
    int t = threadIdx.x, k = blockIdx.x, part = blockIdx.y;
    const float* src = g_tpn + (size_t)k*BS + part*16384;

    float lv[32];
    #pragma unroll
    for (int i = 0; i < 32; i++) lv[i] = -3.4e38f;
    for (int i = 0; i < 64; i++) {
        float v = src[(i<<8) + t];
        if (v > lv[0]) {
            int p = 0;
            while (p < 31 && lv[p+1] < v) { lv[p] = lv[p+1]; p++; }
            lv[p] = v;
        }
    }
    #pragma unroll
    for (int i = 0; i < 32; i++) cand[i*256 + t] = lv[i];
    __syncthreads();

    int ptr = 31;
    for (int r = 0; r < 32; r++) {
        rv[t] = (ptr >= 0) ? cand[ptr*256 + t] : -3.4e38f;
        ri[t] = t;
        __syncthreads();
        for (int off = 128; off > 0; off >>= 1) {
            if (t < off && rv[t+off] > rv[t]) { rv[t] = rv[t+off]; ri[t] = ri[t+off]; }
            __syncthreads();
        }
        if (t == 0) g_cand[k*128 + part*32 + r] = rv[0];
        int win = ri[0];
        __syncthreads();
        if (t == win) ptr--;
    }
}

// ---------------- topk merge ----------------
__global__ void k_topk_merge(float* __restrict__ out) {
    __shared__ float vals[Kn*130];
    __shared__ float sred[64];
    int t = threadIdx.x;  // 64 threads
    for (int i = t; i < Kn*128; i += 64) {
        int k = i >> 7, r = i & 127;
        vals[k*130 + r] = g_cand[i];
    }
    __syncthreads();
    float lsum = 0.f;
    if (t < Kn) {
        const float* row = &vals[t*130];
        int p0 = 0, p1 = 0, p2 = 0, p3 = 0;
        for (int r = 0; r < 32; r++) {
            float v0 = (p0 < 32) ? row[p0]      : -3.4e38f;
            float v1 = (p1 < 32) ? row[32+p1]   : -3.4e38f;
            float v2 = (p2 < 32) ? row[64+p2]   : -3.4e38f;
            float v3 = (p3 < 32) ? row[96+p3]   : -3.4e38f;
            float m = fmaxf(fmaxf(v0, v1), fmaxf(v2, v3));
            lsum += m;
            if (m == v0)      p0++;
            else if (m == v1) p1++;
            else if (m == v2) p2++;
            else              p3++;
        }
    }
    sred[t] = lsum;
    __syncthreads();
    for (int off = 32; off > 0; off >>= 1) {
        if (t < off) sred[t] += sred[t+off];
        __syncthreads();
    }
    if (t == 0) out[257] = -sred[0] * (1.0f/(float)(Kn * (Bn/4)));
}

// ---------------- finalization ----------------
__global__ void k_final(const float* __restrict__ rv2, const float* __restrict__ Wc,
                        const float* __restrict__ bc, float* __restrict__ out) {
    __shared__ float w2c[Hn*NC];
    int t = threadIdx.x;   // 512 threads
    {
        int h = t >> 1, c = t & 1;
        float a = 0.f;
        for (int d = 0; d < Dn; d++) a += rv2[h*Dn + d] * Wc[d*NC + c];
        w2c[t] = a;
    }
    __syncthreads();
    if (t < Bn*NC) {
        int b = t >> 1, c = t & 1;
        float p = 0.f;
        for (int h = 0; h < Hn; h++) p += g_acc1[b*Hn + h] * w2c[h*NC + c];
        out[t] = p * (1.0f/(float)Sn) + bc[c];
    }
    if (t == 256) out[256] = 0.f;
    if (t == 257) out[OUT_AE] = g_ae * (1.0f/(float)(Bn*Sn*Dn));
}

// ---------------- launch ----------------
extern "C" void kernel_launch(void* const* d_in, const int* in_sizes, int n_in,
                              void* d_out, int out_size) {
    const float* f   = (const float*)d_in[0];
    const float* tv  = (const float*)d_in[2];
    const float* rv1 = (const float*)d_in[3];
    const float* rv2 = (const float*)d_in[4];
    const float* Wc  = (const float*)d_in[5];
    const float* bc  = (const float*)d_in[6];
    float* out = (float*)d_out;

    static int attr_set = 0;
    if (!attr_set) {
        cudaFuncSetAttribute(k_topic, cudaFuncAttributeMaxDynamicSharedMemorySize,
                             T_TOT * (int)sizeof(float));
        cudaFuncSetAttribute(k_rec1, cudaFuncAttributeMaxDynamicSharedMemorySize,
                             RS1_FLOATS * (int)sizeof(float));
        attr_set = 1;
    }

    k_init<<<128, 256>>>();
    k_prep<<<50, 256>>>(tv);
    k_far<<<1, 256>>>(out);

    k_topic<<<dim3(8, 128), 512, T_TOT * sizeof(float)>>>(f, out);

    k_topk_part<<<dim3(50, 4), 256>>>();
    k_topk_merge<<<1, 64>>>(out);

    k_rec1<<<1024, 256, RS1_FLOATS * sizeof(float)>>>(rv1, out);

    k_rec2ae<<<1024, 256>>>(rv2);

    k_final<<<1, 512>>>(rv2, Wc, bc, out);
}

// round 10
// speedup vs baseline: 2.4495x; 1.9889x over previous
#include <cuda_runtime.h>
#include <math.h>

// Problem constants
#define Bn   128
#define Dn   256
#define Sn   512
#define Kn   50
#define Hn   256
#define NC   2
#define THRES 0.3f
#define BS   (Bn*Sn)          // 65536

// Output layout (float32):
//  [0..255] pred | [256] 0 | [257] concept_sim | [258] concept_far
//  [259..+B*S*K) topic_prob_nn | [3277059] ae_loss
#define OUT_NN   259
#define OUT_AE   (259 + Bn*Sn*Kn)   // 3277059

// ---------------- device scratch ----------------
__device__ float g_tvnT[Kn*Dn];            // normalized topic vectors, [K][D]
__device__ float g_tpn[(size_t)Kn*BS];     // topic_prob_n, [K][B*S]  (13.1 MB)
__device__ float g_acc1[Bn*Hn];            // sum over s of rec1 (nonzero rows only)
__device__ float g_cand[Kn*128];           // per-part top-32 candidates
__device__ int   g_nzlist[BS];             // compacted nonzero-row indices
__device__ int   g_nnz;                    // count of nonzero rows
__device__ float g_ae;

// ---------------- init ----------------
__global__ void k_init() {
    int i = blockIdx.x*blockDim.x + threadIdx.x;
    if (i < Bn*Hn) g_acc1[i] = 0.f;
    if (i == 0) { g_ae = 0.f; g_nnz = 0; }
}

// ---------------- tv normalization ----------------
__global__ void k_prep(const float* __restrict__ tv) {
    __shared__ float sred[256];
    int k = blockIdx.x, d = threadIdx.x;
    float v = tv[d*Kn + k];
    sred[d] = v*v;
    __syncthreads();
    for (int off = 128; off > 0; off >>= 1) {
        if (d < off) sred[d] += sred[d+off];
        __syncthreads();
    }
    float nrm = sqrtf(sred[0]);
    g_tvnT[k*Dn + d] = v / fmaxf(nrm, 1e-12f);
}

// ---------------- concept_far = (||sum_k tvn_k||^2 - K) / K^2 ----------------
__global__ void k_far(float* __restrict__ out) {
    __shared__ float sred[256];
    int d = threadIdx.x;
    float u = 0.f;
    for (int k = 0; k < Kn; k++) u += g_tvnT[k*Dn + d];
    sred[d] = u*u;
    __syncthreads();
    for (int off = 128; off > 0; off >>= 1) {
        if (d < off) sred[d] += sred[d+off];
        __syncthreads();
    }
    if (d == 0) out[258] = (sred[0] - (float)Kn) / (float)(Kn*Kn);
}

// ================= Kernel 1: topic path + ae base + nz compaction =================
// grid (8, 128): 64 s per block, 512 threads.
#define T_XS   0
#define T_TP   16640
#define T_RED  19904
#define T_RN   20416
#define T_INV  20480
#define T_TOT  20544      // floats -> 82176 bytes
__global__ void __launch_bounds__(512, 2)
k_topic(const float* __restrict__ f, float* __restrict__ out)
{
    extern __shared__ float sm[];
    float* xs  = sm + T_XS;
    float* tp  = sm + T_TP;
    float* red = sm + T_RED;
    float* rn  = sm + T_RN;
    float* inv = sm + T_INV;

    const int tid = threadIdx.x;
    const int b = blockIdx.y;
    const int s0 = blockIdx.x * 64;
    const int bs0 = b*Sn + s0;

    const float* fb = f + (size_t)b*Dn*Sn + s0;
    for (int i = tid; i < 64*Dn; i += 512) {
        int d = i >> 6, sl = i & 63;
        xs[sl*260 + d] = fb[(size_t)d*Sn + sl];
    }
    __syncthreads();

    {
        int s = tid & 63, part = tid >> 6;
        float a = 0.f;
        int d0 = part*32;
        #pragma unroll
        for (int d = d0; d < d0+32; d += 4) {
            float4 v = *reinterpret_cast<const float4*>(&xs[s*260+d]);
            a += v.x*v.x + v.y*v.y + v.z*v.z + v.w*v.w;
        }
        red[part*64 + s] = a;
    }
    __syncthreads();
    if (tid < 64) {
        float nsq = 0.f;
        #pragma unroll
        for (int p = 0; p < 8; p++) nsq += red[p*64 + tid];
        float rv = 1.0f / fmaxf(sqrtf(nsq), 1e-12f);
        rn[tid] = rv;
        // ae base: sum over d of x_n^2 for this row  (= nsq * rv^2)
        float aeb = nsq * rv * rv;
        #pragma unroll
        for (int off = 16; off > 0; off >>= 1)
            aeb += __shfl_xor_sync(0xffffffffu, aeb, off);
        if ((tid & 31) == 0) atomicAdd(&g_ae, aeb);
    }
    __syncthreads();

    const int s = tid & 63, kg = tid >> 6;
    float acc[7];
    #pragma unroll
    for (int j = 0; j < 7; j++) acc[j] = 0.f;
    for (int d = 0; d < Dn; d += 4) {
        float4 x = *reinterpret_cast<const float4*>(&xs[s*260+d]);
        #pragma unroll
        for (int j = 0; j < 7; j++) {
            int k = kg + 8*j;
            int kc = (k < Kn) ? k : 0;
            const float4 w = *reinterpret_cast<const float4*>(&g_tvnT[kc*Dn + d]);
            acc[j] += x.x*w.x + x.y*w.y + x.z*w.z + x.w*w.w;
        }
    }

    float am[7];
    {
        float rns = rn[s];
        float psum = 0.f;
        #pragma unroll
        for (int j = 0; j < 7; j++) {
            int k = kg + 8*j;
            if (k < Kn) {
                float tn = acc[j] * rns;
                g_tpn[(size_t)k*BS + bs0 + s] = tn;
                am[j] = (tn > THRES) ? acc[j] : 0.f;
                psum += am[j];
            } else am[j] = 0.f;
        }
        red[kg*64 + s] = psum;
    }
    __syncthreads();
    if (tid < 64) {
        float t = 0.f;
        #pragma unroll
        for (int p = 0; p < 8; p++) t += red[p*64 + tid];
        inv[tid] = 1.0f / (t + 0.001f + 1e-8f);
        // nonzero row detection: any mask bit -> psum > 0 (tn>THRES implies acc>0)
        if (t > 0.f) {
            int pos = atomicAdd(&g_nnz, 1);
            g_nzlist[pos] = bs0 + tid;
        }
    }
    __syncthreads();
    {
        float iv = inv[s];
        #pragma unroll
        for (int j = 0; j < 7; j++) {
            int k = kg + 8*j;
            if (k < Kn) tp[s*51 + k] = am[j] * iv;
        }
    }
    __syncthreads();

    {
        float* onn = out + OUT_NN + (size_t)bs0 * Kn;
        for (int i = tid; i < 64*Kn; i += 512) {
            int ss = i / 50, k = i - ss*50;
            onn[i] = tp[ss*51 + k];
        }
    }
}

// ================= Kernel 2: sparse rec1+rec2+ae for nonzero rows only =================
// One block per nonzero row (grid-stride). Exact: zero rows contribute
// rec=0 in the reference as well (0*w sums to 0.0, relu(0)=0).
__global__ void __launch_bounds__(256, 2)
k_sparse(const float* __restrict__ f, const float* __restrict__ rv1,
         const float* __restrict__ rv2, const float* __restrict__ out)
{
    __shared__ float nn_s[64];
    __shared__ float r1_s[256];
    __shared__ float red_s[8];
    __shared__ float s_rn;

    const int tid = threadIdx.x;
    const int n = g_nnz;

    for (int idx = blockIdx.x; idx < n; idx += gridDim.x) {
        int bs = g_nzlist[idx];
        int b = bs >> 9, s = bs & 511;

        if (tid < Kn) nn_s[tid] = out[OUT_NN + (size_t)bs*Kn + tid];

        // x column: f[b, d=tid, s]
        float xv = f[((size_t)b*Dn + tid)*Sn + s];
        float v = xv*xv;
        #pragma unroll
        for (int off = 16; off > 0; off >>= 1)
            v += __shfl_xor_sync(0xffffffffu, v, off);
        if ((tid & 31) == 0) red_s[tid >> 5] = v;
        __syncthreads();
        if (tid == 0) {
            float t = 0.f;
            #pragma unroll
            for (int i = 0; i < 8; i++) t += red_s[i];
            s_rn = 1.0f / fmaxf(sqrtf(t), 1e-12f);
        }
        __syncthreads();

        // rec1: thread = h
        float a = 0.f;
        for (int k = 0; k < Kn; k++) a += nn_s[k] * rv1[k*Hn + tid];
        float r1v = fmaxf(a, 0.f);
        r1_s[tid] = r1v;
        atomicAdd(&g_acc1[b*Hn + tid], r1v);
        __syncthreads();

        // rec2: thread = d
        float r2 = 0.f;
        for (int h = 0; h < Hn; h++) r2 += r1_s[h] * rv2[h*Dn + tid];
        float xn = xv * s_rn;
        float e = xn - r2;
        float corr = e*e - xn*xn;   // correction vs ae base
        #pragma unroll
        for (int off = 16; off > 0; off >>= 1)
            corr += __shfl_xor_sync(0xffffffffu, corr, off);
        if ((tid & 31) == 0) red_s[tid >> 5] = corr;
        __syncthreads();
        if (tid == 0) {
            float t = 0.f;
            #pragma unroll
            for (int i = 0; i < 8; i++) t += red_s[i];
            atomicAdd(&g_ae, t);
        }
        __syncthreads();
    }
}

// ---------------- topk part: top-32 of 16384 per (concept, quarter) ----------------
__global__ void k_topk_part() {
    __shared__ float cand[32*256];
    __shared__ float rv[256];
    __shared__ int   ri[256];
    int t = threadIdx.x, k = blockIdx.x, part = blockIdx.y;
    const float* src = g_tpn + (size_t)k*BS + part*16384;

    float lv[32];
    #pragma unroll
    for (int i = 0; i < 32; i++) lv[i] = -3.4e38f;
    for (int i = 0; i < 64; i++) {
        float v = src[(i<<8) + t];
        if (v > lv[0]) {
            int p = 0;
            while (p < 31 && lv[p+1] < v) { lv[p] = lv[p+1]; p++; }
            lv[p] = v;
        }
    }
    #pragma unroll
    for (int i = 0; i < 32; i++) cand[i*256 + t] = lv[i];
    __syncthreads();

    int ptr = 31;
    for (int r = 0; r < 32; r++) {
        rv[t] = (ptr >= 0) ? cand[ptr*256 + t] : -3.4e38f;
        ri[t] = t;
        __syncthreads();
        for (int off = 128; off > 0; off >>= 1) {
            if (t < off && rv[t+off] > rv[t]) { rv[t] = rv[t+off]; ri[t] = ri[t+off]; }
            __syncthreads();
        }
        if (t == 0) g_cand[k*128 + part*32 + r] = rv[0];
        int win = ri[0];
        __syncthreads();
        if (t == win) ptr--;
    }
}

// ---------------- topk merge ----------------
__global__ void k_topk_merge(float* __restrict__ out) {
    __shared__ float vals[Kn*130];
    __shared__ float sred[64];
    int t = threadIdx.x;  // 64 threads
    for (int i = t; i < Kn*128; i += 64) {
        int k = i >> 7, r = i & 127;
        vals[k*130 + r] = g_cand[i];
    }
    __syncthreads();
    float lsum = 0.f;
    if (t < Kn) {
        const float* row = &vals[t*130];
        int p0 = 0, p1 = 0, p2 = 0, p3 = 0;
        for (int r = 0; r < 32; r++) {
            float v0 = (p0 < 32) ? row[p0]      : -3.4e38f;
            float v1 = (p1 < 32) ? row[32+p1]   : -3.4e38f;
            float v2 = (p2 < 32) ? row[64+p2]   : -3.4e38f;
            float v3 = (p3 < 32) ? row[96+p3]   : -3.4e38f;
            float m = fmaxf(fmaxf(v0, v1), fmaxf(v2, v3));
            lsum += m;
            if (m == v0)      p0++;
            else if (m == v1) p1++;
            else if (m == v2) p2++;
            else              p3++;
        }
    }
    sred[t] = lsum;
    __syncthreads();
    for (int off = 32; off > 0; off >>= 1) {
        if (t < off) sred[t] += sred[t+off];
        __syncthreads();
    }
    if (t == 0) out[257] = -sred[0] * (1.0f/(float)(Kn * (Bn/4)));
}

// ---------------- finalization ----------------
__global__ void k_final(const float* __restrict__ rv2, const float* __restrict__ Wc,
                        const float* __restrict__ bc, float* __restrict__ out) {
    __shared__ float w2c[Hn*NC];
    int t = threadIdx.x;   // 512 threads
    {
        int h = t >> 1, c = t & 1;
        float a = 0.f;
        for (int d = 0; d < Dn; d++) a += rv2[h*Dn + d] * Wc[d*NC + c];
        w2c[t] = a;
    }
    __syncthreads();
    if (t < Bn*NC) {
        int b = t >> 1, c = t & 1;
        float p = 0.f;
        for (int h = 0; h < Hn; h++) p += g_acc1[b*Hn + h] * w2c[h*NC + c];
        out[t] = p * (1.0f/(float)Sn) + bc[c];
    }
    if (t == 256) out[256] = 0.f;
    if (t == 257) out[OUT_AE] = g_ae * (1.0f/(float)(Bn*Sn*Dn));
}

// ---------------- launch ----------------
extern "C" void kernel_launch(void* const* d_in, const int* in_sizes, int n_in,
                              void* d_out, int out_size) {
    const float* f   = (const float*)d_in[0];
    const float* tv  = (const float*)d_in[2];
    const float* rv1 = (const float*)d_in[3];
    const float* rv2 = (const float*)d_in[4];
    const float* Wc  = (const float*)d_in[5];
    const float* bc  = (const float*)d_in[6];
    float* out = (float*)d_out;

    static int attr_set = 0;
    if (!attr_set) {
        cudaFuncSetAttribute(k_topic, cudaFuncAttributeMaxDynamicSharedMemorySize,
                             T_TOT * (int)sizeof(float));
        attr_set = 1;
    }

    k_init<<<128, 256>>>();
    k_prep<<<50, 256>>>(tv);
    k_far<<<1, 256>>>(out);

    k_topic<<<dim3(8, 128), 512, T_TOT * sizeof(float)>>>(f, out);

    k_topk_part<<<dim3(50, 4), 256>>>();
    k_topk_merge<<<1, 64>>>(out);

    k_sparse<<<256, 256>>>(f, rv1, rv2, out);

    k_final<<<1, 512>>>(rv2, Wc, bc, out);
}

// round 11
// speedup vs baseline: 3.6286x; 1.4814x over previous
#include <cuda_runtime.h>
#include <math.h>

// Problem constants
#define Bn   128
#define Dn   256
#define Sn   512
#define Kn   50
#define Hn   256
#define NC   2
#define THRES 0.3f
#define BS   (Bn*Sn)          // 65536

// Output layout (float32):
//  [0..255] pred | [256] 0 | [257] concept_sim | [258] concept_far
//  [259..+B*S*K) topic_prob_nn | [3277059] ae_loss
#define OUT_NN   259
#define OUT_AE   (259 + Bn*Sn*Kn)   // 3277059

// ---------------- device scratch ----------------
__device__ float g_tvnT[Kn*Dn];            // normalized topic vectors, [K][D]
__device__ float g_tpn[(size_t)Kn*BS];     // topic_prob_n, [K][B*S]  (13.1 MB)
__device__ float g_acc1[Bn*Hn];            // sum over s of rec1 (nonzero rows only)
__device__ float g_cand[Kn*256];           // per-(k,part) sorted top-32
__device__ int   g_nzlist[BS];             // compacted nonzero-row indices
__device__ int   g_nnz;
__device__ float g_ae;
__device__ float g_sim;

// ---------------- tv normalization + global init ----------------
__global__ void k_prep(const float* __restrict__ tv) {
    __shared__ float sred[256];
    int k = blockIdx.x, d = threadIdx.x;

    // fold global init into this kernel (grid-stride over 50*256 threads)
    int gid = blockIdx.x*256 + threadIdx.x;
    for (int i = gid; i < Bn*Hn; i += 50*256) g_acc1[i] = 0.f;
    if (gid == 0) { g_ae = 0.f; g_sim = 0.f; g_nnz = 0; }

    float v = tv[d*Kn + k];
    sred[d] = v*v;
    __syncthreads();
    for (int off = 128; off > 0; off >>= 1) {
        if (d < off) sred[d] += sred[d+off];
        __syncthreads();
    }
    float nrm = sqrtf(sred[0]);
    g_tvnT[k*Dn + d] = v / fmaxf(nrm, 1e-12f);
}

// ---------------- concept_far = (||sum_k tvn_k||^2 - K) / K^2 ----------------
__global__ void k_far(float* __restrict__ out) {
    __shared__ float sred[256];
    int d = threadIdx.x;
    float u = 0.f;
    for (int k = 0; k < Kn; k++) u += g_tvnT[k*Dn + d];
    sred[d] = u*u;
    __syncthreads();
    for (int off = 128; off > 0; off >>= 1) {
        if (d < off) sred[d] += sred[d+off];
        __syncthreads();
    }
    if (d == 0) out[258] = (sred[0] - (float)Kn) / (float)(Kn*Kn);
}

// ================= Kernel 1: topic path + ae base + nz compaction =================
// grid (8, 128): 64 s per block, 512 threads.
#define T_XS   0
#define T_TP   16640
#define T_RED  19904
#define T_RN   20416
#define T_INV  20480
#define T_TOT  20544      // floats -> 82176 bytes
__global__ void __launch_bounds__(512, 2)
k_topic(const float* __restrict__ f, float* __restrict__ out)
{
    extern __shared__ float sm[];
    float* xs  = sm + T_XS;
    float* tp  = sm + T_TP;
    float* red = sm + T_RED;
    float* rn  = sm + T_RN;
    float* inv = sm + T_INV;

    const int tid = threadIdx.x;
    const int b = blockIdx.y;
    const int s0 = blockIdx.x * 64;
    const int bs0 = b*Sn + s0;

    const float* fb = f + (size_t)b*Dn*Sn + s0;
    for (int i = tid; i < 64*Dn; i += 512) {
        int d = i >> 6, sl = i & 63;
        xs[sl*260 + d] = fb[(size_t)d*Sn + sl];
    }
    __syncthreads();

    {
        int s = tid & 63, part = tid >> 6;
        float a = 0.f;
        int d0 = part*32;
        #pragma unroll
        for (int d = d0; d < d0+32; d += 4) {
            float4 v = *reinterpret_cast<const float4*>(&xs[s*260+d]);
            a += v.x*v.x + v.y*v.y + v.z*v.z + v.w*v.w;
        }
        red[part*64 + s] = a;
    }
    __syncthreads();
    if (tid < 64) {
        float nsq = 0.f;
        #pragma unroll
        for (int p = 0; p < 8; p++) nsq += red[p*64 + tid];
        float rv = 1.0f / fmaxf(sqrtf(nsq), 1e-12f);
        rn[tid] = rv;
        float aeb = nsq * rv * rv;    // sum_d x_n^2 for this row
        #pragma unroll
        for (int off = 16; off > 0; off >>= 1)
            aeb += __shfl_xor_sync(0xffffffffu, aeb, off);
        if ((tid & 31) == 0) atomicAdd(&g_ae, aeb);
    }
    __syncthreads();

    // topic_prob einsum, f32x2 packed over d-pairs
    const int s = tid & 63, kg = tid >> 6;
    unsigned long long accp[7];
    #pragma unroll
    for (int j = 0; j < 7; j++) accp[j] = 0ull;
    for (int d = 0; d < Dn; d += 4) {
        const ulonglong2 xp = *reinterpret_cast<const ulonglong2*>(&xs[s*260+d]);
        #pragma unroll
        for (int j = 0; j < 7; j++) {
            int k = kg + 8*j;
            int kc = (k < Kn) ? k : 0;
            const ulonglong2 wp = *reinterpret_cast<const ulonglong2*>(&g_tvnT[kc*Dn + d]);
            asm("fma.rn.f32x2 %0, %1, %2, %0;" : "+l"(accp[j]) : "l"(xp.x), "l"(wp.x));
            asm("fma.rn.f32x2 %0, %1, %2, %0;" : "+l"(accp[j]) : "l"(xp.y), "l"(wp.y));
        }
    }
    float acc[7];
    #pragma unroll
    for (int j = 0; j < 7; j++) {
        float lo, hi;
        asm("mov.b64 {%0, %1}, %2;" : "=f"(lo), "=f"(hi) : "l"(accp[j]));
        acc[j] = lo + hi;
    }

    float am[7];
    {
        float rns = rn[s];
        float psum = 0.f;
        #pragma unroll
        for (int j = 0; j < 7; j++) {
            int k = kg + 8*j;
            if (k < Kn) {
                float tn = acc[j] * rns;
                g_tpn[(size_t)k*BS + bs0 + s] = tn;
                am[j] = (tn > THRES) ? acc[j] : 0.f;
                psum += am[j];
            } else am[j] = 0.f;
        }
        red[kg*64 + s] = psum;
    }
    __syncthreads();
    if (tid < 64) {
        float t = 0.f;
        #pragma unroll
        for (int p = 0; p < 8; p++) t += red[p*64 + tid];
        inv[tid] = 1.0f / (t + 0.001f + 1e-8f);
        if (t > 0.f) {
            int pos = atomicAdd(&g_nnz, 1);
            g_nzlist[pos] = bs0 + tid;
        }
    }
    __syncthreads();
    {
        float iv = inv[s];
        #pragma unroll
        for (int j = 0; j < 7; j++) {
            int k = kg + 8*j;
            if (k < Kn) tp[s*51 + k] = am[j] * iv;
        }
    }
    __syncthreads();

    {
        float* onn = out + OUT_NN + (size_t)bs0 * Kn;
        for (int i = tid; i < 64*Kn; i += 512) {
            int ss = i / 50, k = i - ss*50;
            onn[i] = tp[ss*51 + k];
        }
    }
}

// ================= sparse rec1+rec2+ae for nonzero rows only =================
__global__ void __launch_bounds__(256, 2)
k_sparse(const float* __restrict__ f, const float* __restrict__ rv1,
         const float* __restrict__ rv2, const float* __restrict__ out)
{
    __shared__ float nn_s[64];
    __shared__ float r1_s[256];
    __shared__ float red_s[8];
    __shared__ float s_rn;

    const int tid = threadIdx.x;
    const int n = g_nnz;

    for (int idx = blockIdx.x; idx < n; idx += gridDim.x) {
        int bs = g_nzlist[idx];
        int b = bs >> 9, s = bs & 511;

        if (tid < Kn) nn_s[tid] = out[OUT_NN + (size_t)bs*Kn + tid];

        float xv = f[((size_t)b*Dn + tid)*Sn + s];
        float v = xv*xv;
        #pragma unroll
        for (int off = 16; off > 0; off >>= 1)
            v += __shfl_xor_sync(0xffffffffu, v, off);
        if ((tid & 31) == 0) red_s[tid >> 5] = v;
        __syncthreads();
        if (tid == 0) {
            float t = 0.f;
            #pragma unroll
            for (int i = 0; i < 8; i++) t += red_s[i];
            s_rn = 1.0f / fmaxf(sqrtf(t), 1e-12f);
        }
        __syncthreads();

        float a = 0.f;
        for (int k = 0; k < Kn; k++) a += nn_s[k] * rv1[k*Hn + tid];
        float r1v = fmaxf(a, 0.f);
        r1_s[tid] = r1v;
        atomicAdd(&g_acc1[b*Hn + tid], r1v);
        __syncthreads();

        float r2 = 0.f;
        for (int h = 0; h < Hn; h++) r2 += r1_s[h] * rv2[h*Dn + tid];
        float xn = xv * s_rn;
        float e = xn - r2;
        float corr = e*e - xn*xn;
        #pragma unroll
        for (int off = 16; off > 0; off >>= 1)
            corr += __shfl_xor_sync(0xffffffffu, corr, off);
        if ((tid & 31) == 0) red_s[tid >> 5] = corr;
        __syncthreads();
        if (tid == 0) {
            float t = 0.f;
            #pragma unroll
            for (int i = 0; i < 8; i++) t += red_s[i];
            atomicAdd(&g_ae, t);
        }
        __syncthreads();
    }
}

// ---------------- topk part: top-32 of 8192 per (concept, eighth) ----------------
// Register bitonic sort-32 per thread (static indices, no local mem),
// then 8-level smem tournament merge (register-staged two-pointer merges).
__global__ void __launch_bounds__(256)
k_topk_part() {
    __shared__ float cand[256*33];
    const int t = threadIdx.x, k = blockIdx.x, part = blockIdx.y;
    const float* src = g_tpn + (size_t)k*BS + part*8192;

    float v[32];
    #pragma unroll
    for (int i = 0; i < 32; i++) v[i] = src[(i<<8) + t];

    // bitonic sort, descending
    #pragma unroll
    for (int sz = 2; sz <= 32; sz <<= 1) {
        #pragma unroll
        for (int st = sz >> 1; st > 0; st >>= 1) {
            #pragma unroll
            for (int i = 0; i < 32; i++) {
                int j = i ^ st;
                if (j > i) {
                    bool desc = ((i & sz) == 0);
                    float a = v[i], b = v[j];
                    bool sw = desc ? (a < b) : (a > b);
                    float lo = sw ? b : a;
                    float hi = sw ? a : b;
                    v[i] = lo; v[j] = hi;
                }
            }
        }
    }
    #pragma unroll
    for (int i = 0; i < 32; i++) cand[t*33 + i] = v[i];
    __syncthreads();

    // tournament merge: 256 sorted lists -> 1, keep top-32 at each node
    #pragma unroll
    for (int lvl = 0; lvl < 8; lvl++) {
        int T = 128 >> lvl;
        if (t < T) {
            int stride = 33 << lvl;
            float* A = &cand[(2*t) * stride];
            float* B = &cand[(2*t + 1) * stride];
            int pa = 0, pb = 0;
            float o[32];
            #pragma unroll
            for (int i = 0; i < 32; i++) {
                float a = A[pa], b = B[pb];
                bool ta = (a >= b);
                o[i] = ta ? a : b;
                pa += ta ? 1 : 0;
                pb += ta ? 0 : 1;
            }
            #pragma unroll
            for (int i = 0; i < 32; i++) A[i] = o[i];
        }
        __syncthreads();
    }

    if (t == 0) {
        #pragma unroll
        for (int i = 0; i < 32; i++)
            g_cand[(k*8 + part)*32 + i] = cand[i];
    }
}

// ---------------- topk merge: 8-way merge of sorted lists per concept ----------------
__global__ void k_topk_merge() {
    __shared__ float vals[256];
    int t = threadIdx.x, k = blockIdx.x;   // 50 blocks, 32 threads
    for (int i = t; i < 256; i += 32) vals[i] = g_cand[k*256 + i];
    __syncwarp();
    if (t == 0) {
        int p0=0,p1=0,p2=0,p3=0,p4=0,p5=0,p6=0,p7=0;
        float lsum = 0.f;
        for (int r = 0; r < 32; r++) {
            float v0 = vals[p0],      v1 = vals[32+p1];
            float v2 = vals[64+p2],   v3 = vals[96+p3];
            float v4 = vals[128+p4],  v5 = vals[160+p5];
            float v6 = vals[192+p6],  v7 = vals[224+p7];
            float m01 = fmaxf(v0,v1), m23 = fmaxf(v2,v3);
            float m45 = fmaxf(v4,v5), m67 = fmaxf(v6,v7);
            float m = fmaxf(fmaxf(m01,m23), fmaxf(m45,m67));
            lsum += m;
            if      (m == v0) p0++;
            else if (m == v1) p1++;
            else if (m == v2) p2++;
            else if (m == v3) p3++;
            else if (m == v4) p4++;
            else if (m == v5) p5++;
            else if (m == v6) p6++;
            else              p7++;
        }
        atomicAdd(&g_sim, lsum);
    }
}

// ---------------- finalization ----------------
__global__ void k_final(const float* __restrict__ rv2, const float* __restrict__ Wc,
                        const float* __restrict__ bc, float* __restrict__ out) {
    __shared__ float w2c[Hn*NC];
    int t = threadIdx.x;   // 512 threads
    {
        int h = t >> 1, c = t & 1;
        float a = 0.f;
        const float4* rp = reinterpret_cast<const float4*>(&rv2[h*Dn]);
        #pragma unroll 8
        for (int q = 0; q < 64; q++) {
            float4 w = rp[q];
            int d = q*4;
            a += w.x*Wc[d*NC+c] + w.y*Wc[(d+1)*NC+c]
               + w.z*Wc[(d+2)*NC+c] + w.w*Wc[(d+3)*NC+c];
        }
        w2c[t] = a;
    }
    __syncthreads();
    if (t < Bn*NC) {
        int b = t >> 1, c = t & 1;
        float p = 0.f;
        const float4* ap = reinterpret_cast<const float4*>(&g_acc1[b*Hn]);
        #pragma unroll 8
        for (int q = 0; q < 64; q++) {
            float4 av = ap[q];
            int h = q*4;
            p += av.x*w2c[h*NC+c] + av.y*w2c[(h+1)*NC+c]
               + av.z*w2c[(h+2)*NC+c] + av.w*w2c[(h+3)*NC+c];
        }
        out[t] = p * (1.0f/(float)Sn) + bc[c];
    }
    if (t == 256) out[256] = 0.f;
    if (t == 257) out[257] = -g_sim * (1.0f/(float)(Kn * (Bn/4)));
    if (t == 258) out[OUT_AE] = g_ae * (1.0f/(float)(Bn*Sn*Dn));
}

// ---------------- launch ----------------
extern "C" void kernel_launch(void* const* d_in, const int* in_sizes, int n_in,
                              void* d_out, int out_size) {
    const float* f   = (const float*)d_in[0];
    const float* tv  = (const float*)d_in[2];
    const float* rv1 = (const float*)d_in[3];
    const float* rv2 = (const float*)d_in[4];
    const float* Wc  = (const float*)d_in[5];
    const float* bc  = (const float*)d_in[6];
    float* out = (float*)d_out;

    static int attr_set = 0;
    if (!attr_set) {
        cudaFuncSetAttribute(k_topic, cudaFuncAttributeMaxDynamicSharedMemorySize,
                             T_TOT * (int)sizeof(float));
        attr_set = 1;
    }

    k_prep<<<50, 256>>>(tv);
    k_far<<<1, 256>>>(out);

    k_topic<<<dim3(8, 128), 512, T_TOT * sizeof(float)>>>(f, out);

    k_topk_part<<<dim3(50, 8), 256>>>();
    k_topk_merge<<<50, 32>>>();

    k_sparse<<<256, 256>>>(f, rv1, rv2, out);

    k_final<<<1, 512>>>(rv2, Wc, bc, out);
}

// round 12
// speedup vs baseline: 4.1658x; 1.1480x over previous
#include <cuda_runtime.h>
#include <math.h>

// Problem constants
#define Bn   128
#define Dn   256
#define Sn   512
#define Kn   50
#define Hn   256
#define NC   2
#define THRES 0.3f
#define BS   (Bn*Sn)          // 65536

// Output layout (float32):
//  [0..255] pred | [256] 0 | [257] concept_sim | [258] concept_far
//  [259..+B*S*K) topic_prob_nn | [3277059] ae_loss
#define OUT_NN   259
#define OUT_AE   (259 + Bn*Sn*Kn)   // 3277059

// ---------------- device scratch ----------------
__device__ float g_tvnT[Kn*Dn];            // normalized topic vectors, [K][D]
__device__ float g_tpn[(size_t)Kn*BS];     // topic_prob_n, [K][B*S]  (13.1 MB)
__device__ float g_acc1[Bn*Hn];            // sum over s of rec1 (nonzero rows only)
__device__ float g_cand[Kn*256];           // per-(k,part) sorted top-32
__device__ int   g_nzlist[BS];             // compacted nonzero-row indices
__device__ int   g_nnz;
__device__ float g_ae;
__device__ float g_sim;

// ---------------- tv normalization + global init ----------------
__global__ void k_prep(const float* __restrict__ tv) {
    __shared__ float sred[256];
    int k = blockIdx.x, d = threadIdx.x;

    int gid = blockIdx.x*256 + threadIdx.x;
    for (int i = gid; i < Bn*Hn; i += 50*256) g_acc1[i] = 0.f;
    if (gid == 0) { g_ae = 0.f; g_sim = 0.f; g_nnz = 0; }

    float v = tv[d*Kn + k];
    sred[d] = v*v;
    __syncthreads();
    for (int off = 128; off > 0; off >>= 1) {
        if (d < off) sred[d] += sred[d+off];
        __syncthreads();
    }
    float nrm = sqrtf(sred[0]);
    g_tvnT[k*Dn + d] = v / fmaxf(nrm, 1e-12f);
}

// ---------------- concept_far ----------------
__global__ void k_far(float* __restrict__ out) {
    __shared__ float sred[256];
    int d = threadIdx.x;
    float u = 0.f;
    for (int k = 0; k < Kn; k++) u += g_tvnT[k*Dn + d];
    sred[d] = u*u;
    __syncthreads();
    for (int off = 128; off > 0; off >>= 1) {
        if (d < off) sred[d] += sred[d+off];
        __syncthreads();
    }
    if (d == 0) out[258] = (sred[0] - (float)Kn) / (float)(Kn*Kn);
}

// ================= Kernel 1: topic path (smem weights, 2s x 4k tiles) =================
// grid (16, 128): 32 s per block, 256 threads, 2 blocks/SM.
// smem floats: xs[32*260] | wsm[50*256] | tp[32*51] | red[16*32] | rn[32] | inv[32]
#define TT_XS   0
#define TT_W    8320
#define TT_TP   21120
#define TT_RED  22752
#define TT_RN   23264
#define TT_INV  23296
#define TT_TOT  23328      // floats -> 93312 bytes
__global__ void __launch_bounds__(256, 2)
k_topic(const float* __restrict__ f, float* __restrict__ out)
{
    extern __shared__ float sm[];
    float* xs  = sm + TT_XS;    // [32][260]
    float* wsm = sm + TT_W;     // [50][256]
    float* tp  = sm + TT_TP;    // [32][51]
    float* red = sm + TT_RED;   // [16][32]
    float* rn  = sm + TT_RN;
    float* inv = sm + TT_INV;

    const int tid = threadIdx.x;
    const int b = blockIdx.y;
    const int s0 = blockIdx.x * 32;
    const int bs0 = b*Sn + s0;

    // stage weights (L2-resident, float4)
    {
        const float4* wsrc = reinterpret_cast<const float4*>(g_tvnT);
        float4* wdst = reinterpret_cast<float4*>(wsm);
        for (int i = tid; i < Kn*Dn/4; i += 256) wdst[i] = wsrc[i];
    }
    // coalesced load of x tile: f is [B,D,S]
    const float* fb = f + (size_t)b*Dn*Sn + s0;
    for (int i = tid; i < 32*Dn; i += 256) {
        int d = i >> 5, sl = i & 31;
        xs[sl*260 + d] = fb[(size_t)d*Sn + sl];
    }
    __syncthreads();

    // per-s inverse norms (8 partials of 32 d each)
    {
        int s = tid & 31, part = tid >> 5;
        float a = 0.f;
        int d0 = part*32;
        #pragma unroll
        for (int d = d0; d < d0+32; d += 4) {
            float4 v = *reinterpret_cast<const float4*>(&xs[s*260+d]);
            a += v.x*v.x + v.y*v.y + v.z*v.z + v.w*v.w;
        }
        red[part*32 + s] = a;
    }
    __syncthreads();
    if (tid < 32) {
        float nsq = 0.f;
        #pragma unroll
        for (int p = 0; p < 8; p++) nsq += red[p*32 + tid];
        float rv = 1.0f / fmaxf(sqrtf(nsq), 1e-12f);
        rn[tid] = rv;
        float aeb = nsq * rv * rv;    // sum_d x_n^2 for this row
        #pragma unroll
        for (int off = 16; off > 0; off >>= 1)
            aeb += __shfl_xor_sync(0xffffffffu, aeb, off);
        if (tid == 0) atomicAdd(&g_ae, aeb);
    }
    __syncthreads();

    // einsum: thread = (s2 = tid&15 -> s in {s2, s2+16}, kg = tid>>4 -> k = kg+16j)
    const int s2 = tid & 15, kg = tid >> 4;
    const int sA = s2, sB = s2 + 16;
    unsigned long long accA[4], accB[4];
    #pragma unroll
    for (int j = 0; j < 4; j++) { accA[j] = 0ull; accB[j] = 0ull; }

    #pragma unroll 2
    for (int d = 0; d < Dn; d += 4) {
        const ulonglong2 xA = *reinterpret_cast<const ulonglong2*>(&xs[sA*260+d]);
        const ulonglong2 xB = *reinterpret_cast<const ulonglong2*>(&xs[sB*260+d]);
        #pragma unroll
        for (int j = 0; j < 4; j++) {
            int k = kg + 16*j;
            int kc = (k < Kn) ? k : 0;
            const ulonglong2 wp = *reinterpret_cast<const ulonglong2*>(&wsm[kc*Dn + d]);
            asm("fma.rn.f32x2 %0, %1, %2, %0;" : "+l"(accA[j]) : "l"(xA.x), "l"(wp.x));
            asm("fma.rn.f32x2 %0, %1, %2, %0;" : "+l"(accA[j]) : "l"(xA.y), "l"(wp.y));
            asm("fma.rn.f32x2 %0, %1, %2, %0;" : "+l"(accB[j]) : "l"(xB.x), "l"(wp.x));
            asm("fma.rn.f32x2 %0, %1, %2, %0;" : "+l"(accB[j]) : "l"(xB.y), "l"(wp.y));
        }
    }

    float dA[4], dB[4], amA[4], amB[4];
    #pragma unroll
    for (int j = 0; j < 4; j++) {
        float lo, hi;
        asm("mov.b64 {%0, %1}, %2;" : "=f"(lo), "=f"(hi) : "l"(accA[j]));
        dA[j] = lo + hi;
        asm("mov.b64 {%0, %1}, %2;" : "=f"(lo), "=f"(hi) : "l"(accB[j]));
        dB[j] = lo + hi;
    }

    {
        float rnA = rn[sA], rnB = rn[sB];
        float psA = 0.f, psB = 0.f;
        #pragma unroll
        for (int j = 0; j < 4; j++) {
            int k = kg + 16*j;
            if (k < Kn) {
                float tnA = dA[j] * rnA;
                float tnB = dB[j] * rnB;
                g_tpn[(size_t)k*BS + bs0 + sA] = tnA;
                g_tpn[(size_t)k*BS + bs0 + sB] = tnB;
                amA[j] = (tnA > THRES) ? dA[j] : 0.f;
                amB[j] = (tnB > THRES) ? dB[j] : 0.f;
                psA += amA[j]; psB += amB[j];
            } else { amA[j] = 0.f; amB[j] = 0.f; }
        }
        red[kg*32 + sA] = psA;
        red[kg*32 + sB] = psB;
    }
    __syncthreads();
    if (tid < 32) {
        float t = 0.f;
        #pragma unroll
        for (int p = 0; p < 16; p++) t += red[p*32 + tid];
        inv[tid] = 1.0f / (t + 0.001f + 1e-8f);
        if (t > 0.f) {
            int pos = atomicAdd(&g_nnz, 1);
            g_nzlist[pos] = bs0 + tid;
        }
    }
    __syncthreads();
    {
        float ivA = inv[sA], ivB = inv[sB];
        #pragma unroll
        for (int j = 0; j < 4; j++) {
            int k = kg + 16*j;
            if (k < Kn) {
                tp[sA*51 + k] = amA[j] * ivA;
                tp[sB*51 + k] = amB[j] * ivB;
            }
        }
    }
    __syncthreads();

    {
        float* onn = out + OUT_NN + (size_t)bs0 * Kn;
        for (int i = tid; i < 32*Kn; i += 256) {
            int ss = i / 50, k = i - ss*50;
            onn[i] = tp[ss*51 + k];
        }
    }
}

// ================= sparse rec1+rec2+ae for nonzero rows only =================
__global__ void __launch_bounds__(256, 2)
k_sparse(const float* __restrict__ f, const float* __restrict__ rv1,
         const float* __restrict__ rv2, const float* __restrict__ out)
{
    __shared__ float nn_s[64];
    __shared__ float r1_s[256];
    __shared__ float red_s[8];
    __shared__ float s_rn;

    const int tid = threadIdx.x;
    const int n = g_nnz;

    for (int idx = blockIdx.x; idx < n; idx += gridDim.x) {
        int bs = g_nzlist[idx];
        int b = bs >> 9, s = bs & 511;

        if (tid < Kn) nn_s[tid] = out[OUT_NN + (size_t)bs*Kn + tid];

        float xv = f[((size_t)b*Dn + tid)*Sn + s];
        float v = xv*xv;
        #pragma unroll
        for (int off = 16; off > 0; off >>= 1)
            v += __shfl_xor_sync(0xffffffffu, v, off);
        if ((tid & 31) == 0) red_s[tid >> 5] = v;
        __syncthreads();
        if (tid == 0) {
            float t = 0.f;
            #pragma unroll
            for (int i = 0; i < 8; i++) t += red_s[i];
            s_rn = 1.0f / fmaxf(sqrtf(t), 1e-12f);
        }
        __syncthreads();

        float a = 0.f;
        for (int k = 0; k < Kn; k++) a += nn_s[k] * rv1[k*Hn + tid];
        float r1v = fmaxf(a, 0.f);
        r1_s[tid] = r1v;
        atomicAdd(&g_acc1[b*Hn + tid], r1v);
        __syncthreads();

        float r2 = 0.f;
        for (int h = 0; h < Hn; h++) r2 += r1_s[h] * rv2[h*Dn + tid];
        float xn = xv * s_rn;
        float e = xn - r2;
        float corr = e*e - xn*xn;
        #pragma unroll
        for (int off = 16; off > 0; off >>= 1)
            corr += __shfl_xor_sync(0xffffffffu, corr, off);
        if ((tid & 31) == 0) red_s[tid >> 5] = corr;
        __syncthreads();
        if (tid == 0) {
            float t = 0.f;
            #pragma unroll
            for (int i = 0; i < 8; i++) t += red_s[i];
            atomicAdd(&g_ae, t);
        }
        __syncthreads();
    }
}

// ---------------- topk part: top-32 of 8192 per (concept, eighth) ----------------
__global__ void __launch_bounds__(256)
k_topk_part() {
    __shared__ float cand[256*33];
    const int t = threadIdx.x, k = blockIdx.x, part = blockIdx.y;
    const float4* src4 = reinterpret_cast<const float4*>(
        g_tpn + (size_t)k*BS + part*8192);

    float v[32];
    #pragma unroll
    for (int i = 0; i < 8; i++) {
        float4 w = src4[(i<<8) + t];     // coalesced LDG.128
        v[4*i]   = w.x; v[4*i+1] = w.y;
        v[4*i+2] = w.z; v[4*i+3] = w.w;
    }

    // bitonic sort-32, descending (static indices — stays in registers)
    #pragma unroll
    for (int sz = 2; sz <= 32; sz <<= 1) {
        #pragma unroll
        for (int st = sz >> 1; st > 0; st >>= 1) {
            #pragma unroll
            for (int i = 0; i < 32; i++) {
                int j = i ^ st;
                if (j > i) {
                    bool desc = ((i & sz) == 0);
                    float a = v[i], b = v[j];
                    bool sw = desc ? (a < b) : (a > b);
                    float lo = sw ? b : a;
                    float hi = sw ? a : b;
                    v[i] = lo; v[j] = hi;
                }
            }
        }
    }
    #pragma unroll
    for (int i = 0; i < 32; i++) cand[t*33 + i] = v[i];
    __syncthreads();

    // tournament merge: 256 sorted lists -> 1, keep top-32 at each node
    #pragma unroll
    for (int lvl = 0; lvl < 8; lvl++) {
        int T = 128 >> lvl;
        if (t < T) {
            int stride = 33 << lvl;
            float* A = &cand[(2*t) * stride];
            float* B = &cand[(2*t + 1) * stride];
            int pa = 0, pb = 0;
            float o[32];
            #pragma unroll
            for (int i = 0; i < 32; i++) {
                float a = A[pa], b = B[pb];
                bool ta = (a >= b);
                o[i] = ta ? a : b;
                pa += ta ? 1 : 0;
                pb += ta ? 0 : 1;
            }
            #pragma unroll
            for (int i = 0; i < 32; i++) A[i] = o[i];
        }
        __syncthreads();
    }

    if (t == 0) {
        #pragma unroll
        for (int i = 0; i < 32; i++)
            g_cand[(k*8 + part)*32 + i] = cand[i];
    }
}

// ---------------- topk merge: 8-way merge per concept ----------------
__global__ void k_topk_merge() {
    __shared__ float vals[256];
    int t = threadIdx.x, k = blockIdx.x;   // 50 blocks, 32 threads
    for (int i = t; i < 256; i += 32) vals[i] = g_cand[k*256 + i];
    __syncwarp();
    if (t == 0) {
        int p0=0,p1=0,p2=0,p3=0,p4=0,p5=0,p6=0,p7=0;
        float lsum = 0.f;
        for (int r = 0; r < 32; r++) {
            float v0 = vals[p0],      v1 = vals[32+p1];
            float v2 = vals[64+p2],   v3 = vals[96+p3];
            float v4 = vals[128+p4],  v5 = vals[160+p5];
            float v6 = vals[192+p6],  v7 = vals[224+p7];
            float m01 = fmaxf(v0,v1), m23 = fmaxf(v2,v3);
            float m45 = fmaxf(v4,v5), m67 = fmaxf(v6,v7);
            float m = fmaxf(fmaxf(m01,m23), fmaxf(m45,m67));
            lsum += m;
            if      (m == v0) p0++;
            else if (m == v1) p1++;
            else if (m == v2) p2++;
            else if (m == v3) p3++;
            else if (m == v4) p4++;
            else if (m == v5) p5++;
            else if (m == v6) p6++;
            else              p7++;
        }
        atomicAdd(&g_sim, lsum);
    }
}

// ---------------- finalization ----------------
__global__ void k_final(const float* __restrict__ rv2, const float* __restrict__ Wc,
                        const float* __restrict__ bc, float* __restrict__ out) {
    __shared__ float w2c[Hn*NC];
    int t = threadIdx.x;   // 512 threads
    {
        int h = t >> 1, c = t & 1;
        float a = 0.f;
        const float4* rp = reinterpret_cast<const float4*>(&rv2[h*Dn]);
        #pragma unroll 8
        for (int q = 0; q < 64; q++) {
            float4 w = rp[q];
            int d = q*4;
            a += w.x*Wc[d*NC+c] + w.y*Wc[(d+1)*NC+c]
               + w.z*Wc[(d+2)*NC+c] + w.w*Wc[(d+3)*NC+c];
        }
        w2c[t] = a;
    }
    __syncthreads();
    if (t < Bn*NC) {
        int b = t >> 1, c = t & 1;
        float p = 0.f;
        const float4* ap = reinterpret_cast<const float4*>(&g_acc1[b*Hn]);
        #pragma unroll 8
        for (int q = 0; q < 64; q++) {
            float4 av = ap[q];
            int h = q*4;
            p += av.x*w2c[h*NC+c] + av.y*w2c[(h+1)*NC+c]
               + av.z*w2c[(h+2)*NC+c] + av.w*w2c[(h+3)*NC+c];
        }
        out[t] = p * (1.0f/(float)Sn) + bc[c];
    }
    if (t == 256) out[256] = 0.f;
    if (t == 257) out[257] = -g_sim * (1.0f/(float)(Kn * (Bn/4)));
    if (t == 258) out[OUT_AE] = g_ae * (1.0f/(float)(Bn*Sn*Dn));
}

// ---------------- launch ----------------
extern "C" void kernel_launch(void* const* d_in, const int* in_sizes, int n_in,
                              void* d_out, int out_size) {
    const float* f   = (const float*)d_in[0];
    const float* tv  = (const float*)d_in[2];
    const float* rv1 = (const float*)d_in[3];
    const float* rv2 = (const float*)d_in[4];
    const float* Wc  = (const float*)d_in[5];
    const float* bc  = (const float*)d_in[6];
    float* out = (float*)d_out;

    static int attr_set = 0;
    if (!attr_set) {
        cudaFuncSetAttribute(k_topic, cudaFuncAttributeMaxDynamicSharedMemorySize,
                             TT_TOT * (int)sizeof(float));
        attr_set = 1;
    }

    k_prep<<<50, 256>>>(tv);
    k_far<<<1, 256>>>(out);

    k_topic<<<dim3(16, 128), 256, TT_TOT * sizeof(float)>>>(f, out);

    k_topk_part<<<dim3(50, 8), 256>>>();
    k_topk_merge<<<50, 32>>>();

    k_sparse<<<256, 256>>>(f, rv1, rv2, out);

    k_final<<<1, 512>>>(rv2, Wc, bc, out);
}

// round 15
// speedup vs baseline: 4.5258x; 1.0864x over previous
#include <cuda_runtime.h>
#include <math.h>

// Problem constants
#define Bn   128
#define Dn   256
#define Sn   512
#define Kn   50
#define Hn   256
#define NC   2
#define THRES 0.3f
#define BS   (Bn*Sn)          // 65536

// Output layout (float32):
//  [0..255] pred | [256] 0 | [257] concept_sim | [258] concept_far
//  [259..+B*S*K) topic_prob_nn | [3277059] ae_loss
#define OUT_NN   259
#define OUT_AE   (259 + Bn*Sn*Kn)   // 3277059

// ---------------- device scratch ----------------
__device__ float g_tvnT[Kn*Dn];            // normalized topic vectors, [K][D]
__device__ float g_tpn[(size_t)Kn*BS];     // topic_prob_n, [K][B*S]  (13.1 MB)
__device__ float g_acc1[Bn*Hn];            // sum over s of rec1 (nonzero rows only)
__device__ float g_cand[Kn*256];           // per-(k,part) sorted top-32
__device__ int   g_nzlist[BS];             // compacted nonzero-row indices
__device__ int   g_nnz;
__device__ float g_ae;
__device__ float g_sim;

// ---------------- tv normalization + global init ----------------
__global__ void k_prep(const float* __restrict__ tv) {
    __shared__ float sred[256];
    int k = blockIdx.x, d = threadIdx.x;

    int gid = blockIdx.x*256 + threadIdx.x;
    for (int i = gid; i < Bn*Hn; i += 50*256) g_acc1[i] = 0.f;
    if (gid == 0) { g_ae = 0.f; g_sim = 0.f; g_nnz = 0; }

    float v = tv[d*Kn + k];
    sred[d] = v*v;
    __syncthreads();
    for (int off = 128; off > 0; off >>= 1) {
        if (d < off) sred[d] += sred[d+off];
        __syncthreads();
    }
    float nrm = sqrtf(sred[0]);
    g_tvnT[k*Dn + d] = v / fmaxf(nrm, 1e-12f);
}

// ---------------- concept_far ----------------
__global__ void k_far(float* __restrict__ out) {
    __shared__ float sred[256];
    int d = threadIdx.x;
    float u = 0.f;
    for (int k = 0; k < Kn; k++) u += g_tvnT[k*Dn + d];
    sred[d] = u*u;
    __syncthreads();
    for (int off = 128; off > 0; off >>= 1) {
        if (d < off) sred[d] += sred[d+off];
        __syncthreads();
    }
    if (d == 0) out[258] = (sred[0] - (float)Kn) / (float)(Kn*Kn);
}

// ================= Kernel 1: topic path (4s x 8k register tiles) =================
// grid (8, 128): 64 s per block, 128 threads, 3 blocks/SM.
// smem floats: xs[64*262] (aliased by tp[64*51] after einsum) | red[512] | rn[64] | inv[64]
#define TP_PITCH 262
#define TT_XS   0
#define TT_RED  16768
#define TT_RN   17280
#define TT_INV  17344
#define TT_TOT  17408      // floats -> 69632 bytes
__global__ void __launch_bounds__(128, 3)
k_topic(const float* __restrict__ f, float* __restrict__ out)
{
    extern __shared__ float sm[];
    float* xs  = sm + TT_XS;    // [64][262]
    float* red = sm + TT_RED;   // [8][64]
    float* rn  = sm + TT_RN;
    float* inv = sm + TT_INV;

    const int tid = threadIdx.x;
    const int b = blockIdx.y;
    const int s0 = blockIdx.x * 64;
    const int bs0 = b*Sn + s0;

    // coalesced load of x tile: f is [B,D,S]
    const float* fb = f + (size_t)b*Dn*Sn + s0;
    for (int i = tid; i < 64*Dn; i += 128) {
        int d = i >> 6, sl = i & 63;
        xs[sl*TP_PITCH + d] = fb[(size_t)d*Sn + sl];
    }
    __syncthreads();

    // per-s inverse norms (2 partials of 128 d each)
    {
        int s = tid & 63, part = tid >> 6;
        float a = 0.f;
        int d0 = part*128;
        #pragma unroll 8
        for (int d = d0; d < d0+128; d += 2) {
            float2 v = *reinterpret_cast<const float2*>(&xs[s*TP_PITCH+d]);
            a += v.x*v.x + v.y*v.y;
        }
        red[part*64 + s] = a;
    }
    __syncthreads();
    if (tid < 64) {
        float nsq = red[tid] + red[64 + tid];
        float rv = 1.0f / fmaxf(sqrtf(nsq), 1e-12f);
        rn[tid] = rv;
        float aeb = nsq * rv * rv;   // sum_d x_n^2 for this row
        #pragma unroll
        for (int off = 16; off > 0; off >>= 1)
            aeb += __shfl_xor_sync(0xffffffffu, aeb, off);
        if ((tid & 31) == 0) atomicAdd(&g_ae, aeb);
    }
    __syncthreads();

    // einsum: thread = (sg = tid&15 -> s = sg+16i, kg = tid>>4 -> k = kg+8j)
    const int sg = tid & 15, kg = tid >> 4;
    int kcl[8];
    #pragma unroll
    for (int j = 0; j < 8; j++) {
        int k = kg + 8*j;
        kcl[j] = (k < Kn) ? k : 0;
    }

    unsigned long long acc[4][8];
    #pragma unroll
    for (int i = 0; i < 4; i++)
        #pragma unroll
        for (int j = 0; j < 8; j++) acc[i][j] = 0ull;

    #pragma unroll 1
    for (int d = 0; d < Dn; d += 4) {
        unsigned long long xlo[4], xhi[4];
        #pragma unroll
        for (int i = 0; i < 4; i++) {
            int base = (sg + 16*i)*TP_PITCH + d;
            xlo[i] = *reinterpret_cast<const unsigned long long*>(&xs[base]);
            xhi[i] = *reinterpret_cast<const unsigned long long*>(&xs[base+2]);
        }
        unsigned long long wlo[8], whi[8];
        #pragma unroll
        for (int j = 0; j < 8; j++) {
            const ulonglong2 wp = *reinterpret_cast<const ulonglong2*>(&g_tvnT[kcl[j]*Dn + d]);
            wlo[j] = wp.x; whi[j] = wp.y;
        }
        #pragma unroll
        for (int i = 0; i < 4; i++)
            #pragma unroll
            for (int j = 0; j < 8; j++) {
                asm("fma.rn.f32x2 %0, %1, %2, %0;" : "+l"(acc[i][j]) : "l"(xlo[i]), "l"(wlo[j]));
                asm("fma.rn.f32x2 %0, %1, %2, %0;" : "+l"(acc[i][j]) : "l"(xhi[i]), "l"(whi[j]));
            }
    }

    float dv[4][8], am[4][8];
    #pragma unroll
    for (int i = 0; i < 4; i++)
        #pragma unroll
        for (int j = 0; j < 8; j++) {
            float lo, hi;
            asm("mov.b64 {%0, %1}, %2;" : "=f"(lo), "=f"(hi) : "l"(acc[i][j]));
            dv[i][j] = lo + hi;
        }

    // tpn write + threshold mask + per-s partial sums
    #pragma unroll
    for (int i = 0; i < 4; i++) {
        int s = sg + 16*i;
        float rns = rn[s];
        float ps = 0.f;
        #pragma unroll
        for (int j = 0; j < 8; j++) {
            int k = kg + 8*j;
            if (k < Kn) {
                float tn = dv[i][j] * rns;
                g_tpn[(size_t)k*BS + bs0 + s] = tn;
                am[i][j] = (tn > THRES) ? dv[i][j] : 0.f;
                ps += am[i][j];
            } else am[i][j] = 0.f;
        }
        red[kg*64 + s] = ps;
    }
    __syncthreads();
    if (tid < 64) {
        float t = 0.f;
        #pragma unroll
        for (int p = 0; p < 8; p++) t += red[p*64 + tid];
        inv[tid] = 1.0f / (t + 0.001f + 1e-8f);
        if (t > 0.f) {
            int pos = atomicAdd(&g_nnz, 1);
            g_nzlist[pos] = bs0 + tid;
        }
    }
    __syncthreads();

    // tp aliases the (now dead) xs region
    float* tpal = sm;   // [64][51]
    #pragma unroll
    for (int i = 0; i < 4; i++) {
        int s = sg + 16*i;
        float iv = inv[s];
        #pragma unroll
        for (int j = 0; j < 8; j++) {
            int k = kg + 8*j;
            if (k < Kn) tpal[s*51 + k] = am[i][j] * iv;
        }
    }
    __syncthreads();

    // write topic_prob_nn to out, coalesced
    {
        float* onn = out + OUT_NN + (size_t)bs0 * Kn;
        for (int i = tid; i < 64*Kn; i += 128) {
            int ss = i / 50, k = i - ss*50;
            onn[i] = tpal[ss*51 + k];
        }
    }
}

// ================= sparse rec1+rec2+ae for nonzero rows only =================
__global__ void __launch_bounds__(256, 2)
k_sparse(const float* __restrict__ f, const float* __restrict__ rv1,
         const float* __restrict__ rv2, const float* __restrict__ out)
{
    __shared__ float nn_s[64];
    __shared__ float r1_s[256];
    __shared__ float red_s[8];
    __shared__ float s_rn;

    const int tid = threadIdx.x;
    const int n = g_nnz;

    for (int idx = blockIdx.x; idx < n; idx += gridDim.x) {
        int bs = g_nzlist[idx];
        int b = bs >> 9, s = bs & 511;

        if (tid < Kn) nn_s[tid] = out[OUT_NN + (size_t)bs*Kn + tid];

        float xv = f[((size_t)b*Dn + tid)*Sn + s];
        float v = xv*xv;
        #pragma unroll
        for (int off = 16; off > 0; off >>= 1)
            v += __shfl_xor_sync(0xffffffffu, v, off);
        if ((tid & 31) == 0) red_s[tid >> 5] = v;
        __syncthreads();
        if (tid == 0) {
            float t = 0.f;
            #pragma unroll
            for (int i = 0; i < 8; i++) t += red_s[i];
            s_rn = 1.0f / fmaxf(sqrtf(t), 1e-12f);
        }
        __syncthreads();

        float a = 0.f;
        for (int k = 0; k < Kn; k++) a += nn_s[k] * rv1[k*Hn + tid];
        float r1v = fmaxf(a, 0.f);
        r1_s[tid] = r1v;
        atomicAdd(&g_acc1[b*Hn + tid], r1v);
        __syncthreads();

        float r2 = 0.f;
        for (int h = 0; h < Hn; h++) r2 += r1_s[h] * rv2[h*Dn + tid];
        float xn = xv * s_rn;
        float e = xn - r2;
        float corr = e*e - xn*xn;
        #pragma unroll
        for (int off = 16; off > 0; off >>= 1)
            corr += __shfl_xor_sync(0xffffffffu, corr, off);
        if ((tid & 31) == 0) red_s[tid >> 5] = corr;
        __syncthreads();
        if (tid == 0) {
            float t = 0.f;
            #pragma unroll
            for (int i = 0; i < 8; i++) t += red_s[i];
            atomicAdd(&g_ae, t);
        }
        __syncthreads();
    }
}

// ---------------- topk part: top-32 of 8192 per (concept, eighth) ----------------
__global__ void __launch_bounds__(256)
k_topk_part() {
    __shared__ float cand[256*33];
    const int t = threadIdx.x, k = blockIdx.x, part = blockIdx.y;
    const float4* src4 = reinterpret_cast<const float4*>(
        g_tpn + (size_t)k*BS + part*8192);

    float v[32];
    #pragma unroll
    for (int i = 0; i < 8; i++) {
        float4 w = src4[(i<<8) + t];     // coalesced LDG.128
        v[4*i]   = w.x; v[4*i+1] = w.y;
        v[4*i+2] = w.z; v[4*i+3] = w.w;
    }

    // bitonic sort-32, descending (static indices — stays in registers)
    #pragma unroll
    for (int sz = 2; sz <= 32; sz <<= 1) {
        #pragma unroll
        for (int st = sz >> 1; st > 0; st >>= 1) {
            #pragma unroll
            for (int i = 0; i < 32; i++) {
                int j = i ^ st;
                if (j > i) {
                    bool desc = ((i & sz) == 0);
                    float a = v[i], b = v[j];
                    bool sw = desc ? (a < b) : (a > b);
                    float lo = sw ? b : a;
                    float hi = sw ? a : b;
                    v[i] = lo; v[j] = hi;
                }
            }
        }
    }
    #pragma unroll
    for (int i = 0; i < 32; i++) cand[t*33 + i] = v[i];
    __syncthreads();

    // tournament merge: 256 sorted lists -> 1, keep top-32 at each node
    #pragma unroll
    for (int lvl = 0; lvl < 8; lvl++) {
        int T = 128 >> lvl;
        if (t < T) {
            int stride = 33 << lvl;
            float* A = &cand[(2*t) * stride];
            float* B = &cand[(2*t + 1) * stride];
            int pa = 0, pb = 0;
            float o[32];
            #pragma unroll
            for (int i = 0; i < 32; i++) {
                float a = A[pa], b = B[pb];
                bool ta = (a >= b);
                o[i] = ta ? a : b;
                pa += ta ? 1 : 0;
                pb += ta ? 0 : 1;
            }
            #pragma unroll
            for (int i = 0; i < 32; i++) A[i] = o[i];
        }
        __syncthreads();
    }

    if (t == 0) {
        #pragma unroll
        for (int i = 0; i < 32; i++)
            g_cand[(k*8 + part)*32 + i] = cand[i];
    }
}

// ---------------- topk merge: 8-way merge per concept ----------------
__global__ void k_topk_merge() {
    __shared__ float vals[256];
    int t = threadIdx.x, k = blockIdx.x;   // 50 blocks, 32 threads
    for (int i = t; i < 256; i += 32) vals[i] = g_cand[k*256 + i];
    __syncwarp();
    if (t == 0) {
        int p0=0,p1=0,p2=0,p3=0,p4=0,p5=0,p6=0,p7=0;
        float lsum = 0.f;
        for (int r = 0; r < 32; r++) {
            float v0 = vals[p0],      v1 = vals[32+p1];
            float v2 = vals[64+p2],   v3 = vals[96+p3];
            float v4 = vals[128+p4],  v5 = vals[160+p5];
            float v6 = vals[192+p6],  v7 = vals[224+p7];
            float m01 = fmaxf(v0,v1), m23 = fmaxf(v2,v3);
            float m45 = fmaxf(v4,v5), m67 = fmaxf(v6,v7);
            float m = fmaxf(fmaxf(m01,m23), fmaxf(m45,m67));
            lsum += m;
            if      (m == v0) p0++;
            else if (m == v1) p1++;
            else if (m == v2) p2++;
            else if (m == v3) p3++;
            else if (m == v4) p4++;
            else if (m == v5) p5++;
            else if (m == v6) p6++;
            else              p7++;
        }
        atomicAdd(&g_sim, lsum);
    }
}

// ---------------- finalization ----------------
__global__ void k_final(const float* __restrict__ rv2, const float* __restrict__ Wc,
                        const float* __restrict__ bc, float* __restrict__ out) {
    __shared__ float w2c[Hn*NC];
    int t = threadIdx.x;   // 512 threads
    {
        int h = t >> 1, c = t & 1;
        float a = 0.f;
        const float4* rp = reinterpret_cast<const float4*>(&rv2[h*Dn]);
        #pragma unroll 8
        for (int q = 0; q < 64; q++) {
            float4 w = rp[q];
            int d = q*4;
            a += w.x*Wc[d*NC+c] + w.y*Wc[(d+1)*NC+c]
               + w.z*Wc[(d+2)*NC+c] + w.w*Wc[(d+3)*NC+c];
        }
        w2c[t] = a;
    }
    __syncthreads();
    if (t < Bn*NC) {
        int b = t >> 1, c = t & 1;
        float p = 0.f;
        const float4* ap = reinterpret_cast<const float4*>(&g_acc1[b*Hn]);
        #pragma unroll 8
        for (int q = 0; q < 64; q++) {
            float4 av = ap[q];
            int h = q*4;
            p += av.x*w2c[h*NC+c] + av.y*w2c[(h+1)*NC+c]
               + av.z*w2c[(h+2)*NC+c] + av.w*w2c[(h+3)*NC+c];
        }
        out[t] = p * (1.0f/(float)Sn) + bc[c];
    }
    if (t == 256) out[256] = 0.f;
    if (t == 257) out[257] = -g_sim * (1.0f/(float)(Kn * (Bn/4)));
    if (t == 258) out[OUT_AE] = g_ae * (1.0f/(float)(Bn*Sn*Dn));
}

// ---------------- launch ----------------
extern "C" void kernel_launch(void* const* d_in, const int* in_sizes, int n_in,
                              void* d_out, int out_size) {
    const float* f   = (const float*)d_in[0];
    const float* tv  = (const float*)d_in[2];
    const float* rv1 = (const float*)d_in[3];
    const float* rv2 = (const float*)d_in[4];
    const float* Wc  = (const float*)d_in[5];
    const float* bc  = (const float*)d_in[6];
    float* out = (float*)d_out;

    static int attr_set = 0;
    if (!attr_set) {
        cudaFuncSetAttribute(k_topic, cudaFuncAttributeMaxDynamicSharedMemorySize,
                             TT_TOT * (int)sizeof(float));
        attr_set = 1;
    }

    k_prep<<<50, 256>>>(tv);
    k_far<<<1, 256>>>(out);

    k_topic<<<dim3(8, 128), 128, TT_TOT * sizeof(float)>>>(f, out);

    k_topk_part<<<dim3(50, 8), 256>>>();
    k_topk_merge<<<50, 32>>>();

    k_sparse<<<256, 256>>>(f, rv1, rv2, out);

    k_final<<<1, 512>>>(rv2, Wc, bc, out);
}

// round 16
// speedup vs baseline: 4.7369x; 1.0466x over previous
#include <cuda_runtime.h>
#include <math.h>

// Problem constants
#define Bn   128
#define Dn   256
#define Sn   512
#define Kn   50
#define Hn   256
#define NC   2
#define THRES 0.3f
#define BS   (Bn*Sn)          // 65536

// Output layout (float32):
//  [0..255] pred | [256] 0 | [257] concept_sim | [258] concept_far
//  [259..+B*S*K) topic_prob_nn | [3277059] ae_loss
#define OUT_NN   259
#define OUT_AE   (259 + Bn*Sn*Kn)   // 3277059

// ---------------- device scratch ----------------
__device__ float g_tvnT[Kn*Dn];            // normalized topic vectors, [K][D]
__device__ float g_tpn[(size_t)Kn*BS];     // topic_prob_n, [K][B*S]  (13.1 MB)
__device__ float g_acc1[Bn*Hn];            // sum over s of rec1 (nonzero rows only)
__device__ float g_cand[Kn*512];           // per-(k,part) sorted top-32 (16 parts)
__device__ int   g_nzlist[BS];             // compacted nonzero-row indices
__device__ int   g_nnz;
__device__ float g_ae;
__device__ float g_sim;

// ---------------- tv normalization + global init ----------------
__global__ void k_prep(const float* __restrict__ tv) {
    __shared__ float sred[256];
    int k = blockIdx.x, d = threadIdx.x;

    int gid = blockIdx.x*256 + threadIdx.x;
    for (int i = gid; i < Bn*Hn; i += 50*256) g_acc1[i] = 0.f;
    if (gid == 0) { g_ae = 0.f; g_sim = 0.f; g_nnz = 0; }

    float v = tv[d*Kn + k];
    sred[d] = v*v;
    __syncthreads();
    for (int off = 128; off > 0; off >>= 1) {
        if (d < off) sred[d] += sred[d+off];
        __syncthreads();
    }
    float nrm = sqrtf(sred[0]);
    g_tvnT[k*Dn + d] = v / fmaxf(nrm, 1e-12f);
}

// ---------------- concept_far ----------------
__global__ void k_far(float* __restrict__ out) {
    __shared__ float sred[256];
    int d = threadIdx.x;
    float u = 0.f;
    for (int k = 0; k < Kn; k++) u += g_tvnT[k*Dn + d];
    sred[d] = u*u;
    __syncthreads();
    for (int off = 128; off > 0; off >>= 1) {
        if (d < off) sred[d] += sred[d+off];
        __syncthreads();
    }
    if (d == 0) out[258] = (sred[0] - (float)Kn) / (float)(Kn*Kn);
}

// ================= Kernel 1: topic path (4s x 8k register tiles) =================
// grid (8, 128): 64 s per block, 128 threads, 3 blocks/SM.
// smem floats: xs[64*262] (aliased by tp[64*51] after einsum) | red[512] | rn[64] | inv[64]
#define TP_PITCH 262
#define TT_XS   0
#define TT_RED  16768
#define TT_RN   17280
#define TT_INV  17344
#define TT_TOT  17408      // floats -> 69632 bytes
__global__ void __launch_bounds__(128, 3)
k_topic(const float* __restrict__ f, float* __restrict__ out)
{
    extern __shared__ float sm[];
    float* xs  = sm + TT_XS;    // [64][262]
    float* red = sm + TT_RED;   // [8][64]
    float* rn  = sm + TT_RN;
    float* inv = sm + TT_INV;

    const int tid = threadIdx.x;
    const int b = blockIdx.y;
    const int s0 = blockIdx.x * 64;
    const int bs0 = b*Sn + s0;

    // ---- load phase: float4 loads, norm fused into registers ----
    // thread owns s-quad f4 = tid&15 (s = 4*f4..4*f4+3), d = dg + 8m.
    {
        const int f4 = tid & 15, dg = tid >> 4;
        const float4* fb4 = reinterpret_cast<const float4*>(f + (size_t)b*Dn*Sn + s0);
        float nq0 = 0.f, nq1 = 0.f, nq2 = 0.f, nq3 = 0.f;
        #pragma unroll 8
        for (int m = 0; m < 32; m++) {
            int d = dg + 8*m;
            float4 w = fb4[d*(Sn/4) + f4];
            xs[(4*f4+0)*TP_PITCH + d] = w.x;
            xs[(4*f4+1)*TP_PITCH + d] = w.y;
            xs[(4*f4+2)*TP_PITCH + d] = w.z;
            xs[(4*f4+3)*TP_PITCH + d] = w.w;
            nq0 += w.x*w.x; nq1 += w.y*w.y; nq2 += w.z*w.z; nq3 += w.w*w.w;
        }
        red[dg*64 + 4*f4+0] = nq0;
        red[dg*64 + 4*f4+1] = nq1;
        red[dg*64 + 4*f4+2] = nq2;
        red[dg*64 + 4*f4+3] = nq3;
    }
    __syncthreads();
    if (tid < 64) {
        float nsq = 0.f;
        #pragma unroll
        for (int p = 0; p < 8; p++) nsq += red[p*64 + tid];
        float rv = 1.0f / fmaxf(sqrtf(nsq), 1e-12f);
        rn[tid] = rv;
        float aeb = nsq * rv * rv;   // sum_d x_n^2 for this row
        #pragma unroll
        for (int off = 16; off > 0; off >>= 1)
            aeb += __shfl_xor_sync(0xffffffffu, aeb, off);
        if ((tid & 31) == 0) atomicAdd(&g_ae, aeb);
    }
    __syncthreads();

    // einsum: thread = (sg = tid&15 -> s = sg+16i, kg = tid>>4 -> k = kg+8j)
    const int sg = tid & 15, kg = tid >> 4;
    int kcl[8];
    #pragma unroll
    for (int j = 0; j < 8; j++) {
        int k = kg + 8*j;
        kcl[j] = (k < Kn) ? k : 0;
    }

    unsigned long long acc[4][8];
    #pragma unroll
    for (int i = 0; i < 4; i++)
        #pragma unroll
        for (int j = 0; j < 8; j++) acc[i][j] = 0ull;

    #pragma unroll 2
    for (int d = 0; d < Dn; d += 4) {
        unsigned long long xlo[4], xhi[4];
        #pragma unroll
        for (int i = 0; i < 4; i++) {
            int base = (sg + 16*i)*TP_PITCH + d;
            xlo[i] = *reinterpret_cast<const unsigned long long*>(&xs[base]);
            xhi[i] = *reinterpret_cast<const unsigned long long*>(&xs[base+2]);
        }
        unsigned long long wlo[8], whi[8];
        #pragma unroll
        for (int j = 0; j < 8; j++) {
            const ulonglong2 wp = *reinterpret_cast<const ulonglong2*>(&g_tvnT[kcl[j]*Dn + d]);
            wlo[j] = wp.x; whi[j] = wp.y;
        }
        #pragma unroll
        for (int i = 0; i < 4; i++)
            #pragma unroll
            for (int j = 0; j < 8; j++) {
                asm("fma.rn.f32x2 %0, %1, %2, %0;" : "+l"(acc[i][j]) : "l"(xlo[i]), "l"(wlo[j]));
                asm("fma.rn.f32x2 %0, %1, %2, %0;" : "+l"(acc[i][j]) : "l"(xhi[i]), "l"(whi[j]));
            }
    }

    float dv[4][8], am[4][8];
    #pragma unroll
    for (int i = 0; i < 4; i++)
        #pragma unroll
        for (int j = 0; j < 8; j++) {
            float lo, hi;
            asm("mov.b64 {%0, %1}, %2;" : "=f"(lo), "=f"(hi) : "l"(acc[i][j]));
            dv[i][j] = lo + hi;
        }

    // tpn write + threshold mask + per-s partial sums
    #pragma unroll
    for (int i = 0; i < 4; i++) {
        int s = sg + 16*i;
        float rns = rn[s];
        float ps = 0.f;
        #pragma unroll
        for (int j = 0; j < 8; j++) {
            int k = kg + 8*j;
            if (k < Kn) {
                float tn = dv[i][j] * rns;
                g_tpn[(size_t)k*BS + bs0 + s] = tn;
                am[i][j] = (tn > THRES) ? dv[i][j] : 0.f;
                ps += am[i][j];
            } else am[i][j] = 0.f;
        }
        red[kg*64 + s] = ps;
    }
    __syncthreads();
    if (tid < 64) {
        float t = 0.f;
        #pragma unroll
        for (int p = 0; p < 8; p++) t += red[p*64 + tid];
        inv[tid] = 1.0f / (t + 0.001f + 1e-8f);
        if (t > 0.f) {
            int pos = atomicAdd(&g_nnz, 1);
            g_nzlist[pos] = bs0 + tid;
        }
    }
    __syncthreads();

    // tp aliases the (now dead) xs region
    float* tpal = sm;   // [64][51]
    #pragma unroll
    for (int i = 0; i < 4; i++) {
        int s = sg + 16*i;
        float iv = inv[s];
        #pragma unroll
        for (int j = 0; j < 8; j++) {
            int k = kg + 8*j;
            if (k < Kn) tpal[s*51 + k] = am[i][j] * iv;
        }
    }
    __syncthreads();

    // write topic_prob_nn to out, coalesced
    {
        float* onn = out + OUT_NN + (size_t)bs0 * Kn;
        for (int i = tid; i < 64*Kn; i += 128) {
            int ss = i / 50, k = i - ss*50;
            onn[i] = tpal[ss*51 + k];
        }
    }
}

// ================= sparse rec1+rec2+ae for nonzero rows only =================
__global__ void __launch_bounds__(256, 2)
k_sparse(const float* __restrict__ f, const float* __restrict__ rv1,
         const float* __restrict__ rv2, const float* __restrict__ out)
{
    __shared__ float nn_s[64];
    __shared__ float r1_s[256];
    __shared__ float red_s[8];
    __shared__ float s_rn;

    const int tid = threadIdx.x;
    const int n = g_nnz;

    for (int idx = blockIdx.x; idx < n; idx += gridDim.x) {
        int bs = g_nzlist[idx];
        int b = bs >> 9, s = bs & 511;

        if (tid < Kn) nn_s[tid] = out[OUT_NN + (size_t)bs*Kn + tid];

        float xv = f[((size_t)b*Dn + tid)*Sn + s];
        float v = xv*xv;
        #pragma unroll
        for (int off = 16; off > 0; off >>= 1)
            v += __shfl_xor_sync(0xffffffffu, v, off);
        if ((tid & 31) == 0) red_s[tid >> 5] = v;
        __syncthreads();
        if (tid == 0) {
            float t = 0.f;
            #pragma unroll
            for (int i = 0; i < 8; i++) t += red_s[i];
            s_rn = 1.0f / fmaxf(sqrtf(t), 1e-12f);
        }
        __syncthreads();

        float a = 0.f;
        for (int k = 0; k < Kn; k++) a += nn_s[k] * rv1[k*Hn + tid];
        float r1v = fmaxf(a, 0.f);
        r1_s[tid] = r1v;
        atomicAdd(&g_acc1[b*Hn + tid], r1v);
        __syncthreads();

        float r2 = 0.f;
        for (int h = 0; h < Hn; h++) r2 += r1_s[h] * rv2[h*Dn + tid];
        float xn = xv * s_rn;
        float e = xn - r2;
        float corr = e*e - xn*xn;
        #pragma unroll
        for (int off = 16; off > 0; off >>= 1)
            corr += __shfl_xor_sync(0xffffffffu, corr, off);
        if ((tid & 31) == 0) red_s[tid >> 5] = corr;
        __syncthreads();
        if (tid == 0) {
            float t = 0.f;
            #pragma unroll
            for (int i = 0; i < 8; i++) t += red_s[i];
            atomicAdd(&g_ae, t);
        }
        __syncthreads();
    }
}

// ---------------- topk part: top-32 of 4096 per (concept, sixteenth) ----------------
// 16 values/thread: bitonic sort-16, one full 16+16->32 merge, then 7 top-32 merges.
__global__ void __launch_bounds__(256)
k_topk_part() {
    __shared__ float cand[256*17];   // 17.4 KB
    const int t = threadIdx.x, k = blockIdx.x, part = blockIdx.y;
    const float4* src4 = reinterpret_cast<const float4*>(
        g_tpn + (size_t)k*BS + part*4096);

    float v[16];
    #pragma unroll
    for (int i = 0; i < 4; i++) {
        float4 w = src4[(i<<8) + t];     // coalesced LDG.128
        v[4*i]   = w.x; v[4*i+1] = w.y;
        v[4*i+2] = w.z; v[4*i+3] = w.w;
    }

    // bitonic sort-16, descending (static indices — registers only)
    #pragma unroll
    for (int sz = 2; sz <= 16; sz <<= 1) {
        #pragma unroll
        for (int st = sz >> 1; st > 0; st >>= 1) {
            #pragma unroll
            for (int i = 0; i < 16; i++) {
                int j = i ^ st;
                if (j > i) {
                    bool desc = ((i & sz) == 0);
                    float a = v[i], b = v[j];
                    bool sw = desc ? (a < b) : (a > b);
                    float lo = sw ? b : a;
                    float hi = sw ? a : b;
                    v[i] = lo; v[j] = hi;
                }
            }
        }
    }
    #pragma unroll
    for (int i = 0; i < 16; i++) cand[t*17 + i] = v[i];
    __syncthreads();

    // level 0: full merge 16+16 -> 32 (keeps everything)
    if (t < 128) {
        float* A = &cand[(2*t) * 17];
        float* B = &cand[(2*t + 1) * 17];
        int pa = 0, pb = 0;
        float o[32];
        #pragma unroll
        for (int i = 0; i < 32; i++) {
            float a = (pa < 16) ? A[pa] : -3.4e38f;
            float b = (pb < 16) ? B[pb] : -3.4e38f;
            bool ta = (a >= b);
            o[i] = ta ? a : b;
            pa += ta ? 1 : 0;
            pb += ta ? 0 : 1;
        }
        #pragma unroll
        for (int i = 0; i < 32; i++) A[i] = o[i];
    }
    __syncthreads();

    // levels 1..7: merge 32+32 -> top-32 (lists at stride 34<<(lvl-1))
    #pragma unroll
    for (int lvl = 1; lvl <= 7; lvl++) {
        int T = 128 >> lvl;
        if (t < T) {
            int stride = 34 << (lvl - 1);
            float* A = &cand[(2*t) * stride];
            float* B = &cand[(2*t + 1) * stride];
            int pa = 0, pb = 0;
            float o[32];
            #pragma unroll
            for (int i = 0; i < 32; i++) {
                float a = A[pa], b = B[pb];
                bool ta = (a >= b);
                o[i] = ta ? a : b;
                pa += ta ? 1 : 0;
                pb += ta ? 0 : 1;
            }
            #pragma unroll
            for (int i = 0; i < 32; i++) A[i] = o[i];
        }
        __syncthreads();
    }

    if (t == 0) {
        #pragma unroll
        for (int i = 0; i < 32; i++)
            g_cand[(k*16 + part)*32 + i] = cand[i];
    }
}

// ---------------- topk merge: 16-way merge per concept ----------------
__global__ void k_topk_merge() {
    __shared__ float vals[512];
    int t = threadIdx.x, k = blockIdx.x;   // 50 blocks, 32 threads
    for (int i = t; i < 512; i += 32) vals[i] = g_cand[k*512 + i];
    __syncwarp();
    if (t == 0) {
        int p[16];
        #pragma unroll
        for (int j = 0; j < 16; j++) p[j] = 0;
        float lsum = 0.f;
        for (int r = 0; r < 32; r++) {
            float m = -3.4e38f;
            int win = 0;
            #pragma unroll
            for (int j = 0; j < 16; j++) {
                float vj = vals[j*32 + p[j]];
                if (vj > m) { m = vj; win = j; }
            }
            lsum += m;
            p[win]++;
        }
        atomicAdd(&g_sim, lsum);
    }
}

// ---------------- finalization ----------------
__global__ void k_final(const float* __restrict__ rv2, const float* __restrict__ Wc,
                        const float* __restrict__ bc, float* __restrict__ out) {
    __shared__ float w2c[Hn*NC];
    int t = threadIdx.x;   // 512 threads
    {
        int h = t >> 1, c = t & 1;
        float a = 0.f;
        const float4* rp = reinterpret_cast<const float4*>(&rv2[h*Dn]);
        #pragma unroll 8
        for (int q = 0; q < 64; q++) {
            float4 w = rp[q];
            int d = q*4;
            a += w.x*Wc[d*NC+c] + w.y*Wc[(d+1)*NC+c]
               + w.z*Wc[(d+2)*NC+c] + w.w*Wc[(d+3)*NC+c];
        }
        w2c[t] = a;
    }
    __syncthreads();
    if (t < Bn*NC) {
        int b = t >> 1, c = t & 1;
        float p = 0.f;
        const float4* ap = reinterpret_cast<const float4*>(&g_acc1[b*Hn]);
        #pragma unroll 8
        for (int q = 0; q < 64; q++) {
            float4 av = ap[q];
            int h = q*4;
            p += av.x*w2c[h*NC+c] + av.y*w2c[(h+1)*NC+c]
               + av.z*w2c[(h+2)*NC+c] + av.w*w2c[(h+3)*NC+c];
        }
        out[t] = p * (1.0f/(float)Sn) + bc[c];
    }
    if (t == 256) out[256] = 0.f;
    if (t == 257) out[257] = -g_sim * (1.0f/(float)(Kn * (Bn/4)));
    if (t == 258) out[OUT_AE] = g_ae * (1.0f/(float)(Bn*Sn*Dn));
}

// ---------------- launch ----------------
extern "C" void kernel_launch(void* const* d_in, const int* in_sizes, int n_in,
                              void* d_out, int out_size) {
    const float* f   = (const float*)d_in[0];
    const float* tv  = (const float*)d_in[2];
    const float* rv1 = (const float*)d_in[3];
    const float* rv2 = (const float*)d_in[4];
    const float* Wc  = (const float*)d_in[5];
    const float* bc  = (const float*)d_in[6];
    float* out = (float*)d_out;

    static int attr_set = 0;
    if (!attr_set) {
        cudaFuncSetAttribute(k_topic, cudaFuncAttributeMaxDynamicSharedMemorySize,
                             TT_TOT * (int)sizeof(float));
        attr_set = 1;
    }

    k_prep<<<50, 256>>>(tv);
    k_far<<<1, 256>>>(out);

    k_topic<<<dim3(8, 128), 128, TT_TOT * sizeof(float)>>>(f, out);

    k_topk_part<<<dim3(50, 16), 256>>>();
    k_topk_merge<<<50, 32>>>();

    k_sparse<<<256, 256>>>(f, rv1, rv2, out);

    k_final<<<1, 512>>>(rv2, Wc, bc, out);
}